// round 3
// baseline (speedup 1.0000x reference)
#include <cuda_runtime.h>

#define NN 20000
#define EE 320000
#define CC 128
#define BB 20
#define RCUT_F 5.0f
#define EPS_F 1e-8f

// ---------------- scratch (device globals; no allocation allowed) ----------------
__device__ float g_x  [NN * 3 * CC];   // per-node context net output [N,3C]
__device__ float g_q1 [NN * CC];       // q + dq (accumulated)
__device__ float g_mu1[NN * 3 * CC];   // mu + dmu (accumulated)
__device__ float g_muV[NN * 3 * CC];
__device__ float g_muW[NN * 3 * CC];

__device__ __forceinline__ void red4(float* p, float4 v) {
    asm volatile("red.global.add.v4.f32 [%0], {%1,%2,%3,%4};"
                 :: "l"(p), "f"(v.x), "f"(v.y), "f"(v.z), "f"(v.w) : "memory");
}
__device__ __forceinline__ float siluf(float x) {
    return x * (1.0f / (1.0f + __expf(-x)));
}

// ============================================================================
// K1: per-node context net  x = silu(q@W1+b1)@W2+b2 ; also seed g_q1=q, g_mu1=mu
// 32 nodes per block, 128 threads (thread = channel), transposed smem tiles.
// ============================================================================
#define NPB1 32
#define STR1 36   // padded row stride (floats), 144B = 16B aligned

__global__ __launch_bounds__(128) void k_context(
    const float* __restrict__ q, const float* __restrict__ mu,
    const float* __restrict__ W1, const float* __restrict__ b1,
    const float* __restrict__ W2, const float* __restrict__ b2)
{
    __shared__ float sqT[CC * STR1];   // [k][n]
    __shared__ float shT[CC * STR1];   // [k][n]
    const int c    = threadIdx.x;
    const int base = blockIdx.x * NPB1;

    // load q rows (coalesced) into transposed tile; seed g_q1
    #pragma unroll
    for (int n = 0; n < NPB1; n++) {
        float v = q[(base + n) * CC + c];
        sqT[c * STR1 + n] = v;
        g_q1[(base + n) * CC + c] = v;
    }
    // seed g_mu1 = mu (coalesced block copy)
    for (int t = threadIdx.x; t < NPB1 * 3 * CC; t += blockDim.x)
        g_mu1[base * 3 * CC + t] = mu[base * 3 * CC + t];
    __syncthreads();

    // layer 1: h = silu(q @ W1 + b1)
    float acc[NPB1];
    {
        float bb = b1[c];
        #pragma unroll
        for (int n = 0; n < NPB1; n++) acc[n] = bb;
        for (int k = 0; k < CC; k++) {
            float w = W1[k * CC + c];
            const float4* row = reinterpret_cast<const float4*>(&sqT[k * STR1]);
            #pragma unroll
            for (int m = 0; m < NPB1 / 4; m++) {
                float4 v = row[m];
                acc[4*m+0] = fmaf(v.x, w, acc[4*m+0]);
                acc[4*m+1] = fmaf(v.y, w, acc[4*m+1]);
                acc[4*m+2] = fmaf(v.z, w, acc[4*m+2]);
                acc[4*m+3] = fmaf(v.w, w, acc[4*m+3]);
            }
        }
    }
    #pragma unroll
    for (int n = 0; n < NPB1; n++) shT[c * STR1 + n] = siluf(acc[n]);
    __syncthreads();

    // layer 2: x = h @ W2 + b2  (3 output groups of 128)
    for (int g = 0; g < 3; g++) {
        float a2[NPB1];
        float bb = b2[g * CC + c];
        #pragma unroll
        for (int n = 0; n < NPB1; n++) a2[n] = bb;
        for (int k = 0; k < CC; k++) {
            float w = W2[k * 3 * CC + g * CC + c];
            const float4* row = reinterpret_cast<const float4*>(&shT[k * STR1]);
            #pragma unroll
            for (int m = 0; m < NPB1 / 4; m++) {
                float4 v = row[m];
                a2[4*m+0] = fmaf(v.x, w, a2[4*m+0]);
                a2[4*m+1] = fmaf(v.y, w, a2[4*m+1]);
                a2[4*m+2] = fmaf(v.z, w, a2[4*m+2]);
                a2[4*m+3] = fmaf(v.w, w, a2[4*m+3]);
            }
        }
        #pragma unroll
        for (int n = 0; n < NPB1; n++)
            g_x[(base + n) * 3 * CC + g * CC + c] = a2[n];
    }
}

// ============================================================================
// K2: edge kernel. One warp per edge; lane handles 4 channels.
// Fused: fcut + RBF filter GEMV (B=20) + gather x[j], mu[j] + red.v4 scatter.
// ============================================================================
__global__ __launch_bounds__(256) void k_edge(
    const int*   __restrict__ eidx,     // [2,E]
    const float* __restrict__ ew,       // [E]
    const float* __restrict__ evs,      // [E,3]
    const float* __restrict__ attrs,    // [E,B]
    const float* __restrict__ Wf,       // [B,3C]
    const float* __restrict__ bf,       // [3C]
    const float* __restrict__ mu)       // [N,3,C]
{
    const int lane = threadIdx.x & 31;
    const int e = blockIdx.x * (blockDim.x >> 5) + (threadIdx.x >> 5);
    if (e >= EE) return;

    const int i = eidx[e];
    const int j = eidx[EE + e];
    const float w = ew[e];
    const float fcut = (w < RCUT_F)
        ? 0.5f * (__cosf((3.14159265358979f / RCUT_F) * w) + 1.0f) : 0.0f;

    float a  = (lane < BB) ? attrs[e * BB + lane] : 0.0f;
    float vv = (lane < 3)  ? evs[e * 3 + lane]    : 0.0f;
    const float ev0 = __shfl_sync(0xFFFFFFFFu, vv, 0);
    const float ev1 = __shfl_sync(0xFFFFFFFFu, vv, 1);
    const float ev2 = __shfl_sync(0xFFFFFFFFu, vv, 2);

    const int c0 = lane * 4;
    float4 wq = *reinterpret_cast<const float4*>(&bf[c0]);
    float4 wR = *reinterpret_cast<const float4*>(&bf[CC + c0]);
    float4 wm = *reinterpret_cast<const float4*>(&bf[2 * CC + c0]);

    #pragma unroll
    for (int b = 0; b < BB; b++) {
        float ab = __shfl_sync(0xFFFFFFFFu, a, b);
        float4 f0 = *reinterpret_cast<const float4*>(&Wf[b * 3 * CC + c0]);
        float4 f1 = *reinterpret_cast<const float4*>(&Wf[b * 3 * CC + CC + c0]);
        float4 f2 = *reinterpret_cast<const float4*>(&Wf[b * 3 * CC + 2 * CC + c0]);
        wq.x = fmaf(ab, f0.x, wq.x); wq.y = fmaf(ab, f0.y, wq.y);
        wq.z = fmaf(ab, f0.z, wq.z); wq.w = fmaf(ab, f0.w, wq.w);
        wR.x = fmaf(ab, f1.x, wR.x); wR.y = fmaf(ab, f1.y, wR.y);
        wR.z = fmaf(ab, f1.z, wR.z); wR.w = fmaf(ab, f1.w, wR.w);
        wm.x = fmaf(ab, f2.x, wm.x); wm.y = fmaf(ab, f2.y, wm.y);
        wm.z = fmaf(ab, f2.z, wm.z); wm.w = fmaf(ab, f2.w, wm.w);
    }
    wq.x *= fcut; wq.y *= fcut; wq.z *= fcut; wq.w *= fcut;
    wR.x *= fcut; wR.y *= fcut; wR.z *= fcut; wR.w *= fcut;
    wm.x *= fcut; wm.y *= fcut; wm.z *= fcut; wm.w *= fcut;

    const float4* xb = reinterpret_cast<const float4*>(&g_x[j * 3 * CC]);
    float4 x0 = xb[lane];
    float4 x1 = xb[32 + lane];
    float4 x2 = xb[64 + lane];

    // dq scatter
    float4 dq = make_float4(x0.x * wq.x, x0.y * wq.y, x0.z * wq.z, x0.w * wq.w);
    red4(&g_q1[i * CC + c0], dq);

    // dmu scatter
    float4 cR = make_float4(x1.x * wR.x, x1.y * wR.y, x1.z * wR.z, x1.w * wR.w);
    float4 cm = make_float4(x2.x * wm.x, x2.y * wm.y, x2.z * wm.z, x2.w * wm.w);
    const float4* mub = reinterpret_cast<const float4*>(&mu[j * 3 * CC]);
    #pragma unroll
    for (int v = 0; v < 3; v++) {
        float evv = (v == 0) ? ev0 : (v == 1) ? ev1 : ev2;
        float4 mj = mub[v * 32 + lane];
        float4 dm = make_float4(fmaf(cm.x, mj.x, cR.x * evv),
                                fmaf(cm.y, mj.y, cR.y * evv),
                                fmaf(cm.z, mj.z, cR.z * evv),
                                fmaf(cm.w, mj.w, cR.w * evv));
        red4(&g_mu1[(i * 3 + v) * CC + c0], dm);
    }
}

// ============================================================================
// K3a: mu_mix = mu1 @ W_mix  -> muV, muW. Treat mu1 as [3N,128] matrix.
// ============================================================================
#define RPB3 32
__global__ __launch_bounds__(128) void k_mumix(const float* __restrict__ Wmix)
{
    __shared__ float sT[CC * STR1];
    const int d = threadIdx.x;
    const int base = blockIdx.x * RPB3;

    #pragma unroll
    for (int r = 0; r < RPB3; r++)
        sT[d * STR1 + r] = g_mu1[(base + r) * CC + d];
    __syncthreads();

    for (int g = 0; g < 2; g++) {
        float acc[RPB3];
        #pragma unroll
        for (int r = 0; r < RPB3; r++) acc[r] = 0.0f;
        for (int k = 0; k < CC; k++) {
            float w = Wmix[k * 2 * CC + g * CC + d];
            const float4* row = reinterpret_cast<const float4*>(&sT[k * STR1]);
            #pragma unroll
            for (int m = 0; m < RPB3 / 4; m++) {
                float4 v = row[m];
                acc[4*m+0] = fmaf(v.x, w, acc[4*m+0]);
                acc[4*m+1] = fmaf(v.y, w, acc[4*m+1]);
                acc[4*m+2] = fmaf(v.z, w, acc[4*m+2]);
                acc[4*m+3] = fmaf(v.w, w, acc[4*m+3]);
            }
        }
        float* dst = (g == 0) ? g_muV : g_muW;
        #pragma unroll
        for (int r = 0; r < RPB3; r++)
            dst[(base + r) * CC + d] = acc[r];
    }
}

// ============================================================================
// K3b: mixing MLP + final outputs. 16 nodes/block, 128 threads (thread = d).
// ============================================================================
#define NPB4 16
#define STR4 20   // 80B rows, 16B aligned

__global__ __launch_bounds__(128) void k_mixout(
    const float* __restrict__ Wm1, const float* __restrict__ bm1,
    const float* __restrict__ Wm2, const float* __restrict__ bm2,
    float* __restrict__ out_q, float* __restrict__ out_mu)
{
    __shared__ float ctxT[2 * CC * STR4];  // [k=0..255][n]
    __shared__ float hT[CC * STR4];        // [k=0..127][n]
    const int d = threadIdx.x;
    const int base = blockIdx.x * NPB4;

    float scal[NPB4];
    #pragma unroll
    for (int n = 0; n < NPB4; n++) {
        const int node = base + n;
        float q1v = g_q1[node * CC + d];
        float v0 = g_muV[(node * 3 + 0) * CC + d];
        float v1 = g_muV[(node * 3 + 1) * CC + d];
        float v2 = g_muV[(node * 3 + 2) * CC + d];
        float w0 = g_muW[(node * 3 + 0) * CC + d];
        float w1 = g_muW[(node * 3 + 1) * CC + d];
        float w2 = g_muW[(node * 3 + 2) * CC + d];
        float vn = sqrtf(fmaf(v0, v0, fmaf(v1, v1, fmaf(v2, v2, EPS_F))));
        scal[n] = fmaf(v0, w0, fmaf(v1, w1, v2 * w2));
        ctxT[d * STR4 + n] = q1v;
        ctxT[(CC + d) * STR4 + n] = vn;
    }
    __syncthreads();

    // layer 1: h = silu(ctx @ Wm1 + bm1)
    {
        float acc[NPB4];
        float bb = bm1[d];
        #pragma unroll
        for (int n = 0; n < NPB4; n++) acc[n] = bb;
        for (int k = 0; k < 2 * CC; k++) {
            float w = Wm1[k * CC + d];
            const float4* row = reinterpret_cast<const float4*>(&ctxT[k * STR4]);
            #pragma unroll
            for (int m = 0; m < NPB4 / 4; m++) {
                float4 v = row[m];
                acc[4*m+0] = fmaf(v.x, w, acc[4*m+0]);
                acc[4*m+1] = fmaf(v.y, w, acc[4*m+1]);
                acc[4*m+2] = fmaf(v.z, w, acc[4*m+2]);
                acc[4*m+3] = fmaf(v.w, w, acc[4*m+3]);
            }
        }
        #pragma unroll
        for (int n = 0; n < NPB4; n++) hT[d * STR4 + n] = siluf(acc[n]);
    }
    __syncthreads();

    // layer 2 group g: y_g = h @ Wm2[:, g*C + d] + bm2
    auto gemm_g = [&](int g, float* acc) {
        float bb = bm2[g * CC + d];
        #pragma unroll
        for (int n = 0; n < NPB4; n++) acc[n] = bb;
        for (int k = 0; k < CC; k++) {
            float w = Wm2[k * 3 * CC + g * CC + d];
            const float4* row = reinterpret_cast<const float4*>(&hT[k * STR4]);
            #pragma unroll
            for (int m = 0; m < NPB4 / 4; m++) {
                float4 v = row[m];
                acc[4*m+0] = fmaf(v.x, w, acc[4*m+0]);
                acc[4*m+1] = fmaf(v.y, w, acc[4*m+1]);
                acc[4*m+2] = fmaf(v.z, w, acc[4*m+2]);
                acc[4*m+3] = fmaf(v.w, w, acc[4*m+3]);
            }
        }
    };

    float y2[NPB4];
    gemm_g(2, y2);          // dqmu_intra

    float acc[NPB4];
    gemm_g(0, acc);         // dq_intra -> q_out
    #pragma unroll
    for (int n = 0; n < NPB4; n++) {
        const int node = base + n;
        float q1v = g_q1[node * CC + d];
        out_q[node * CC + d] = q1v + acc[n] + y2[n] * scal[n];
    }

    gemm_g(1, acc);         // dmu_intra -> mu_out
    #pragma unroll
    for (int n = 0; n < NPB4; n++) {
        const int node = base + n;
        #pragma unroll
        for (int v = 0; v < 3; v++) {
            float mw  = g_muW[(node * 3 + v) * CC + d];
            float m1  = g_mu1[(node * 3 + v) * CC + d];
            out_mu[(node * 3 + v) * CC + d] = fmaf(acc[n], mw, m1);
        }
    }
}

// ============================================================================
extern "C" void kernel_launch(void* const* d_in, const int* in_sizes, int n_in,
                              void* d_out, int out_size)
{
    const float* q        = (const float*)d_in[0];
    const float* mu       = (const float*)d_in[1];
    const int*   eidx     = (const int*)  d_in[2];
    const float* ew       = (const float*)d_in[3];
    const float* evs      = (const float*)d_in[4];
    const float* attrs    = (const float*)d_in[5];
    const float* Wf       = (const float*)d_in[6];
    const float* bf       = (const float*)d_in[7];
    const float* W1       = (const float*)d_in[8];
    const float* b1       = (const float*)d_in[9];
    const float* W2       = (const float*)d_in[10];
    const float* b2       = (const float*)d_in[11];
    const float* Wmix     = (const float*)d_in[12];
    const float* Wm1      = (const float*)d_in[13];
    const float* bm1      = (const float*)d_in[14];
    const float* Wm2      = (const float*)d_in[15];
    const float* bm2      = (const float*)d_in[16];

    float* out_q  = (float*)d_out;
    float* out_mu = out_q + (size_t)NN * CC;

    k_context<<<NN / NPB1, 128>>>(q, mu, W1, b1, W2, b2);
    k_edge<<<(EE + 7) / 8, 256>>>(eidx, ew, evs, attrs, Wf, bf, mu);
    k_mumix<<<(3 * NN) / RPB3, 128>>>(Wmix);
    k_mixout<<<NN / NPB4, 128>>>(Wm1, bm1, Wm2, bm2, out_q, out_mu);
}

// round 6
// speedup vs baseline: 1.2631x; 1.2631x over previous
#include <cuda_runtime.h>
#include <cstdint>

#define NN 20000
#define EE 320000
#define CC 128
#define BB 20
#define RCUT_F 5.0f
#define EPS_F 1e-8f

// ---------------- scratch (device globals; no allocation allowed) ----------------
__device__ float g_x  [NN * 3 * CC];   // per-node context net output [N,3C]
__device__ float g_q1 [NN * CC];       // q + dq (accumulated)
__device__ float g_mu1[NN * 3 * CC];   // mu + dmu (accumulated)
__device__ float g_muV[NN * 3 * CC];
__device__ float g_muW[NN * 3 * CC];

// ---------------- helpers ----------------
__device__ __forceinline__ void red4(float* p, float4 v) {
    asm volatile("red.global.add.v4.f32 [%0], {%1,%2,%3,%4};"
                 :: "l"(p), "f"(v.x), "f"(v.y), "f"(v.z), "f"(v.w) : "memory");
}
__device__ __forceinline__ float siluf(float x) {
    return x * (1.0f / (1.0f + __expf(-x)));
}
// packed fp32x2 FMA (Blackwell FFMA2): d = a*b + d
__device__ __forceinline__ void fma2(uint64_t& d, uint64_t a, uint64_t b) {
    asm("fma.rn.f32x2 %0, %1, %2, %0;" : "+l"(d) : "l"(a), "l"(b));
}
__device__ __forceinline__ uint64_t pk(float lo, float hi) {
    uint64_t r; asm("mov.b64 %0, {%1, %2};" : "=l"(r) : "f"(lo), "f"(hi)); return r;
}
__device__ __forceinline__ uint64_t bcast2(float w) {
    uint64_t r; asm("mov.b64 %0, {%1, %1};" : "=l"(r) : "f"(w)); return r;
}
__device__ __forceinline__ float2 unpk(uint64_t p) {
    float2 r; asm("mov.b64 {%0, %1}, %2;" : "=f"(r.x), "=f"(r.y) : "l"(p)); return r;
}

// ============================================================================
// K1: context net  x = silu(q@W1+b1)@W2+b2 ; seed g_q1=q, g_mu1=mu
// 32 nodes/block, 128 threads (thread = out channel). FFMA2 packed pairs.
// ============================================================================
#define NPB1 32
#define STR1 36   // padded row stride (floats), 144B (16B aligned rows)

__global__ __launch_bounds__(128) void k_context(
    const float* __restrict__ q, const float* __restrict__ mu,
    const float* __restrict__ W1, const float* __restrict__ b1,
    const float* __restrict__ W2, const float* __restrict__ b2)
{
    __shared__ __align__(16) float sqT[CC * STR1];   // [k][n]
    __shared__ __align__(16) float shT[CC * STR1];   // [k][n]
    const int c    = threadIdx.x;
    const int base = blockIdx.x * NPB1;

    #pragma unroll
    for (int n = 0; n < NPB1; n++) {
        float v = q[(base + n) * CC + c];
        sqT[c * STR1 + n] = v;
        g_q1[(base + n) * CC + c] = v;
    }
    for (int t = threadIdx.x; t < NPB1 * 3 * CC; t += 128)
        g_mu1[base * 3 * CC + t] = mu[base * 3 * CC + t];
    __syncthreads();

    // layer 1: h = silu(q @ W1 + b1)
    uint64_t acc[16];
    {
        float bb = b1[c];
        uint64_t bi = pk(bb, bb);
        #pragma unroll
        for (int m = 0; m < 16; m++) acc[m] = bi;
        #pragma unroll 4
        for (int k = 0; k < CC; k++) {
            uint64_t ww = bcast2(W1[k * CC + c]);
            const ulonglong2* row = reinterpret_cast<const ulonglong2*>(&sqT[k * STR1]);
            #pragma unroll
            for (int m = 0; m < 8; m++) {
                ulonglong2 v = row[m];
                fma2(acc[2*m],   v.x, ww);
                fma2(acc[2*m+1], v.y, ww);
            }
        }
    }
    #pragma unroll
    for (int m = 0; m < 16; m++) {
        float2 p = unpk(acc[m]);
        shT[c * STR1 + 2*m]     = siluf(p.x);
        shT[c * STR1 + 2*m + 1] = siluf(p.y);
    }
    __syncthreads();

    // layer 2: x = h @ W2 + b2   (3 groups of 128 outputs)
    #pragma unroll 1
    for (int g = 0; g < 3; g++) {
        float bb = b2[g * CC + c];
        uint64_t bi = pk(bb, bb);
        uint64_t a2[16];
        #pragma unroll
        for (int m = 0; m < 16; m++) a2[m] = bi;
        #pragma unroll 4
        for (int k = 0; k < CC; k++) {
            uint64_t ww = bcast2(W2[k * 3 * CC + g * CC + c]);
            const ulonglong2* row = reinterpret_cast<const ulonglong2*>(&shT[k * STR1]);
            #pragma unroll
            for (int m = 0; m < 8; m++) {
                ulonglong2 v = row[m];
                fma2(a2[2*m],   v.x, ww);
                fma2(a2[2*m+1], v.y, ww);
            }
        }
        #pragma unroll
        for (int m = 0; m < 16; m++) {
            float2 p = unpk(a2[m]);
            g_x[(base + 2*m)     * 3 * CC + g * CC + c] = p.x;
            g_x[(base + 2*m + 1) * 3 * CC + g * CC + c] = p.y;
        }
    }
}

// ============================================================================
// K2: edge kernel. One warp per 4 edges (weight reads amortized), Wf in smem.
// Fused: fcut + RBF filter GEMV (FFMA2) + gather x[j],mu[j] + red.v4 scatter.
// ============================================================================
#define EPW 4
#define EWARPS 8

__global__ __launch_bounds__(256) void k_edge(
    const int*   __restrict__ eidx,     // [2,E]
    const float* __restrict__ ew,       // [E]
    const float* __restrict__ evs,      // [E,3]
    const float* __restrict__ attrs,    // [E,B]
    const float* __restrict__ Wf,       // [B,3C]
    const float* __restrict__ bf,       // [3C]
    const float* __restrict__ mu)       // [N,3,C]
{
    __shared__ __align__(16) float sWf[BB * 3 * CC];   // 30720 B
    __shared__ __align__(16) float sbf[3 * CC];        //  1536 B

    for (int t = threadIdx.x; t < BB * 3 * CC / 4; t += 256)
        reinterpret_cast<float4*>(sWf)[t] = reinterpret_cast<const float4*>(Wf)[t];
    for (int t = threadIdx.x; t < 3 * CC / 4; t += 256)
        reinterpret_cast<float4*>(sbf)[t] = reinterpret_cast<const float4*>(bf)[t];
    __syncthreads();

    const int lane  = threadIdx.x & 31;
    const int wid   = threadIdx.x >> 5;
    const int c0    = lane * 4;
    const int nwarp = gridDim.x * EWARPS;

    const float4 bq = *reinterpret_cast<const float4*>(&sbf[c0]);
    const float4 bR = *reinterpret_cast<const float4*>(&sbf[CC + c0]);
    const float4 bm = *reinterpret_cast<const float4*>(&sbf[2 * CC + c0]);

    for (int gidx = blockIdx.x * EWARPS + wid; gidx < EE / EPW; gidx += nwarp) {
        const int e0 = gidx * EPW;
        int ii[EPW], jj[EPW];
        float fc[EPW], av[EPW];
        #pragma unroll
        for (int t = 0; t < EPW; t++) {
            ii[t] = eidx[e0 + t];
            jj[t] = eidx[EE + e0 + t];
            float w = ew[e0 + t];
            fc[t] = (w < RCUT_F)
                ? 0.5f * (__cosf((3.14159265358979f / RCUT_F) * w) + 1.0f) : 0.0f;
            av[t] = (lane < BB) ? attrs[(e0 + t) * BB + lane] : 0.0f;
        }

        uint64_t acc[EPW][6];
        #pragma unroll
        for (int t = 0; t < EPW; t++) {
            acc[t][0] = pk(bq.x, bq.y); acc[t][1] = pk(bq.z, bq.w);
            acc[t][2] = pk(bR.x, bR.y); acc[t][3] = pk(bR.z, bR.w);
            acc[t][4] = pk(bm.x, bm.y); acc[t][5] = pk(bm.z, bm.w);
        }

        #pragma unroll
        for (int b = 0; b < BB; b++) {
            ulonglong2 f0 = *reinterpret_cast<const ulonglong2*>(&sWf[b * 3 * CC + c0]);
            ulonglong2 f1 = *reinterpret_cast<const ulonglong2*>(&sWf[b * 3 * CC + CC + c0]);
            ulonglong2 f2 = *reinterpret_cast<const ulonglong2*>(&sWf[b * 3 * CC + 2 * CC + c0]);
            #pragma unroll
            for (int t = 0; t < EPW; t++) {
                uint64_t aw = bcast2(__shfl_sync(0xFFFFFFFFu, av[t], b));
                fma2(acc[t][0], f0.x, aw); fma2(acc[t][1], f0.y, aw);
                fma2(acc[t][2], f1.x, aw); fma2(acc[t][3], f1.y, aw);
                fma2(acc[t][4], f2.x, aw); fma2(acc[t][5], f2.y, aw);
            }
        }

        #pragma unroll
        for (int t = 0; t < EPW; t++) {
            const int e = e0 + t;
            const float f = fc[t];
            const float ev0 = evs[e * 3 + 0];
            const float ev1 = evs[e * 3 + 1];
            const float ev2 = evs[e * 3 + 2];

            float2 wq0 = unpk(acc[t][0]), wq1 = unpk(acc[t][1]);
            float2 wR0 = unpk(acc[t][2]), wR1 = unpk(acc[t][3]);
            float2 wm0 = unpk(acc[t][4]), wm1 = unpk(acc[t][5]);

            const float4* xb = reinterpret_cast<const float4*>(&g_x[jj[t] * 3 * CC]);
            float4 x0 = xb[lane];
            float4 x1 = xb[32 + lane];
            float4 x2 = xb[64 + lane];

            float4 dq = make_float4(x0.x * wq0.x * f, x0.y * wq0.y * f,
                                    x0.z * wq1.x * f, x0.w * wq1.y * f);
            red4(&g_q1[ii[t] * CC + c0], dq);

            float4 cR = make_float4(x1.x * wR0.x * f, x1.y * wR0.y * f,
                                    x1.z * wR1.x * f, x1.w * wR1.y * f);
            float4 cm = make_float4(x2.x * wm0.x * f, x2.y * wm0.y * f,
                                    x2.z * wm1.x * f, x2.w * wm1.y * f);

            const float4* mub = reinterpret_cast<const float4*>(&mu[jj[t] * 3 * CC]);
            #pragma unroll
            for (int v = 0; v < 3; v++) {
                float evv = (v == 0) ? ev0 : (v == 1) ? ev1 : ev2;
                float4 mj = mub[v * 32 + lane];
                float4 dm = make_float4(fmaf(cm.x, mj.x, cR.x * evv),
                                        fmaf(cm.y, mj.y, cR.y * evv),
                                        fmaf(cm.z, mj.z, cR.z * evv),
                                        fmaf(cm.w, mj.w, cR.w * evv));
                red4(&g_mu1[(ii[t] * 3 + v) * CC + c0], dm);
            }
        }
    }
}

// ============================================================================
// K3a: mu_mix = mu1 @ W_mix -> muV, muW. mu1 treated as [3N,128].
// ============================================================================
#define RPB3 32
__global__ __launch_bounds__(128) void k_mumix(const float* __restrict__ Wmix)
{
    __shared__ __align__(16) float sT[CC * STR1];
    const int d = threadIdx.x;
    const int base = blockIdx.x * RPB3;

    #pragma unroll
    for (int r = 0; r < RPB3; r++)
        sT[d * STR1 + r] = g_mu1[(base + r) * CC + d];
    __syncthreads();

    #pragma unroll 1
    for (int g = 0; g < 2; g++) {
        uint64_t acc[16];
        #pragma unroll
        for (int m = 0; m < 16; m++) acc[m] = 0ull;
        #pragma unroll 4
        for (int k = 0; k < CC; k++) {
            uint64_t ww = bcast2(Wmix[k * 2 * CC + g * CC + d]);
            const ulonglong2* row = reinterpret_cast<const ulonglong2*>(&sT[k * STR1]);
            #pragma unroll
            for (int m = 0; m < 8; m++) {
                ulonglong2 v = row[m];
                fma2(acc[2*m],   v.x, ww);
                fma2(acc[2*m+1], v.y, ww);
            }
        }
        float* dst = (g == 0) ? g_muV : g_muW;
        #pragma unroll
        for (int m = 0; m < 16; m++) {
            float2 p = unpk(acc[m]);
            dst[(base + 2*m)     * CC + d] = p.x;
            dst[(base + 2*m + 1) * CC + d] = p.y;
        }
    }
}

// ============================================================================
// K3b: mixing MLP + final outputs. 32 nodes/block, 128 threads (thread = d).
// One smem buffer reused for ctx (256 rows) then h (128 rows).
// ============================================================================
#define NPB4 32

__global__ __launch_bounds__(128) void k_mixout(
    const float* __restrict__ Wm1, const float* __restrict__ bm1,
    const float* __restrict__ Wm2, const float* __restrict__ bm2,
    float* __restrict__ out_q, float* __restrict__ out_mu)
{
    __shared__ __align__(16) float buf[2 * CC * STR1];  // 36.9 KB, ctx then h
    const int d = threadIdx.x;
    const int base = blockIdx.x * NPB4;

    // build transposed ctx tile: rows 0..127 = q1, rows 128..255 = |mu_V|
    #pragma unroll
    for (int n = 0; n < NPB4; n++) {
        const int node = base + n;
        float q1v = g_q1[node * CC + d];
        float v0 = g_muV[(node * 3 + 0) * CC + d];
        float v1 = g_muV[(node * 3 + 1) * CC + d];
        float v2 = g_muV[(node * 3 + 2) * CC + d];
        float vn = sqrtf(fmaf(v0, v0, fmaf(v1, v1, fmaf(v2, v2, EPS_F))));
        buf[d * STR1 + n] = q1v;
        buf[(CC + d) * STR1 + n] = vn;
    }
    __syncthreads();

    // layer 1: h = silu(ctx @ Wm1 + bm1)
    uint64_t acc[16];
    {
        float bb = bm1[d];
        uint64_t bi = pk(bb, bb);
        #pragma unroll
        for (int m = 0; m < 16; m++) acc[m] = bi;
        #pragma unroll 4
        for (int k = 0; k < 2 * CC; k++) {
            uint64_t ww = bcast2(Wm1[k * CC + d]);
            const ulonglong2* row = reinterpret_cast<const ulonglong2*>(&buf[k * STR1]);
            #pragma unroll
            for (int m = 0; m < 8; m++) {
                ulonglong2 v = row[m];
                fma2(acc[2*m],   v.x, ww);
                fma2(acc[2*m+1], v.y, ww);
            }
        }
    }
    __syncthreads();   // all ctx reads done; reuse buf rows 0..127 for h
    #pragma unroll
    for (int m = 0; m < 16; m++) {
        float2 p = unpk(acc[m]);
        buf[d * STR1 + 2*m]     = siluf(p.x);
        buf[d * STR1 + 2*m + 1] = siluf(p.y);
    }
    __syncthreads();

    // layer 2 group-GEMV over h (rows 0..127 of buf)
    auto gemm_g = [&](int g, uint64_t* a) {
        float bb = bm2[g * CC + d];
        uint64_t bi = pk(bb, bb);
        #pragma unroll
        for (int m = 0; m < 16; m++) a[m] = bi;
        #pragma unroll 4
        for (int k = 0; k < CC; k++) {
            uint64_t ww = bcast2(Wm2[k * 3 * CC + g * CC + d]);
            const ulonglong2* row = reinterpret_cast<const ulonglong2*>(&buf[k * STR1]);
            #pragma unroll
            for (int m = 0; m < 8; m++) {
                ulonglong2 v = row[m];
                fma2(a[2*m],   v.x, ww);
                fma2(a[2*m+1], v.y, ww);
            }
        }
    };

    {
        uint64_t a2[16], a0[16];
        gemm_g(2, a2);      // dqmu_intra
        gemm_g(0, a0);      // dq_intra
        #pragma unroll
        for (int m = 0; m < 16; m++) {
            float2 p0 = unpk(a0[m]);
            float2 p2 = unpk(a2[m]);
            #pragma unroll
            for (int h = 0; h < 2; h++) {
                const int node = base + 2*m + h;
                float v0 = g_muV[(node * 3 + 0) * CC + d];
                float v1 = g_muV[(node * 3 + 1) * CC + d];
                float v2 = g_muV[(node * 3 + 2) * CC + d];
                float w0 = g_muW[(node * 3 + 0) * CC + d];
                float w1 = g_muW[(node * 3 + 1) * CC + d];
                float w2 = g_muW[(node * 3 + 2) * CC + d];
                float scal = fmaf(v0, w0, fmaf(v1, w1, v2 * w2));
                float q1v  = g_q1[node * CC + d];
                float y0 = h ? p0.y : p0.x;
                float y2 = h ? p2.y : p2.x;
                out_q[node * CC + d] = q1v + y0 + y2 * scal;
            }
        }
    }
    {
        uint64_t a1[16];
        gemm_g(1, a1);      // dmu_intra
        #pragma unroll
        for (int m = 0; m < 16; m++) {
            float2 p1 = unpk(a1[m]);
            #pragma unroll
            for (int h = 0; h < 2; h++) {
                const int node = base + 2*m + h;
                float y1 = h ? p1.y : p1.x;
                #pragma unroll
                for (int v = 0; v < 3; v++) {
                    float mw = g_muW[(node * 3 + v) * CC + d];
                    float m1 = g_mu1[(node * 3 + v) * CC + d];
                    out_mu[(node * 3 + v) * CC + d] = fmaf(y1, mw, m1);
                }
            }
        }
    }
}

// ============================================================================
extern "C" void kernel_launch(void* const* d_in, const int* in_sizes, int n_in,
                              void* d_out, int out_size)
{
    const float* q     = (const float*)d_in[0];
    const float* mu    = (const float*)d_in[1];
    const int*   eidx  = (const int*)  d_in[2];
    const float* ew    = (const float*)d_in[3];
    const float* evs   = (const float*)d_in[4];
    const float* attrs = (const float*)d_in[5];
    const float* Wf    = (const float*)d_in[6];
    const float* bf    = (const float*)d_in[7];
    const float* W1    = (const float*)d_in[8];
    const float* b1    = (const float*)d_in[9];
    const float* W2    = (const float*)d_in[10];
    const float* b2    = (const float*)d_in[11];
    const float* Wmix  = (const float*)d_in[12];
    const float* Wm1   = (const float*)d_in[13];
    const float* bm1   = (const float*)d_in[14];
    const float* Wm2   = (const float*)d_in[15];
    const float* bm2   = (const float*)d_in[16];

    float* out_q  = (float*)d_out;
    float* out_mu = out_q + (size_t)NN * CC;

    k_context<<<NN / NPB1, 128>>>(q, mu, W1, b1, W2, b2);
    k_edge<<<1184, 256>>>(eidx, ew, evs, attrs, Wf, bf, mu);
    k_mumix<<<(3 * NN) / RPB3, 128>>>(Wmix);
    k_mixout<<<NN / NPB4, 128>>>(Wm1, bm1, Wm2, bm2, out_q, out_mu);
}

// round 9
// speedup vs baseline: 1.3816x; 1.0938x over previous
#include <cuda_runtime.h>
#include <cstdint>

#define NN 20000
#define EE 320000
#define CC 128
#define BB 20
#define RCUT_F 5.0f
#define EPS_F 1e-8f

// ---------------- scratch (device globals; no allocation allowed) ----------------
__device__ float g_x  [NN * 3 * CC];   // per-node context net output [N,3C]
__device__ float g_q1 [NN * CC];       // q + dq (accumulated)
__device__ float g_mu1[NN * 3 * CC];   // mu + dmu (accumulated)
__device__ float g_muV[NN * 3 * CC];
__device__ float g_muW[NN * 3 * CC];

// ---------------- helpers ----------------
__device__ __forceinline__ void red4(float* p, float4 v) {
    asm volatile("red.global.add.v4.f32 [%0], {%1,%2,%3,%4};"
                 :: "l"(p), "f"(v.x), "f"(v.y), "f"(v.z), "f"(v.w) : "memory");
}
__device__ __forceinline__ float siluf(float x) {
    return x * (1.0f / (1.0f + __expf(-x)));
}
// packed fp32x2 FMA (Blackwell FFMA2): d = a*b + d
__device__ __forceinline__ void fma2(uint64_t& d, uint64_t a, uint64_t b) {
    asm("fma.rn.f32x2 %0, %1, %2, %0;" : "+l"(d) : "l"(a), "l"(b));
}
__device__ __forceinline__ uint64_t pk(float lo, float hi) {
    uint64_t r; asm("mov.b64 %0, {%1, %2};" : "=l"(r) : "f"(lo), "f"(hi)); return r;
}
__device__ __forceinline__ uint64_t bcast2(float w) {
    uint64_t r; asm("mov.b64 %0, {%1, %1};" : "=l"(r) : "f"(w)); return r;
}
__device__ __forceinline__ float2 unpk(uint64_t p) {
    float2 r; asm("mov.b64 {%0, %1}, %2;" : "=f"(r.x), "=f"(r.y) : "l"(p)); return r;
}

// Node-GEMV tiling: 256 threads, 16 nodes/block.
// thread = (d = tid&127 output channel, h = tid>>7 node-half); each half owns 8 nodes.
#define NPB 16
#define NH  8
#define STR 20   // padded tile row stride in floats (80B; 16B-aligned subrows)

// ============================================================================
// K1: context net  x = silu(q@W1+b1)@W2+b2 ; seed g_q1=q, g_mu1=mu
// ============================================================================
__global__ __launch_bounds__(256) void k_context(
    const float* __restrict__ q, const float* __restrict__ mu,
    const float* __restrict__ W1, const float* __restrict__ b1,
    const float* __restrict__ W2, const float* __restrict__ b2)
{
    __shared__ __align__(16) float sqT[CC * STR];   // [k][n]
    __shared__ __align__(16) float shT[CC * STR];   // [k][n]
    const int tid  = threadIdx.x;
    const int d    = tid & 127;
    const int h    = tid >> 7;
    const int base = blockIdx.x * NPB;

    // load q rows (coalesced over d) into transposed tile; seed g_q1
    #pragma unroll
    for (int n2 = 0; n2 < NH; n2++) {
        const int n = n2 * 2 + h;
        float v = q[(base + n) * CC + d];
        sqT[d * STR + n] = v;
        g_q1[(base + n) * CC + d] = v;
    }
    // seed g_mu1 = mu
    {
        const float4* src = reinterpret_cast<const float4*>(&mu[base * 3 * CC]);
        float4* dst = reinterpret_cast<float4*>(&g_mu1[base * 3 * CC]);
        #pragma unroll
        for (int t = tid; t < NPB * 3 * CC / 4; t += 256) dst[t] = src[t];
    }
    __syncthreads();

    // layer 1: h = silu(q @ W1 + b1)    (each thread: channel d, nodes h*8..h*8+7)
    uint64_t acc[4];
    {
        float bb = b1[d];
        uint64_t bi = pk(bb, bb);
        #pragma unroll
        for (int m = 0; m < 4; m++) acc[m] = bi;
        #pragma unroll 8
        for (int k = 0; k < CC; k++) {
            uint64_t ww = bcast2(W1[k * CC + d]);
            const ulonglong2* row = reinterpret_cast<const ulonglong2*>(&sqT[k * STR + h * NH]);
            ulonglong2 v0 = row[0], v1 = row[1];
            fma2(acc[0], v0.x, ww); fma2(acc[1], v0.y, ww);
            fma2(acc[2], v1.x, ww); fma2(acc[3], v1.y, ww);
        }
    }
    #pragma unroll
    for (int m = 0; m < 4; m++) {
        float2 p = unpk(acc[m]);
        shT[d * STR + h * NH + 2*m]     = siluf(p.x);
        shT[d * STR + h * NH + 2*m + 1] = siluf(p.y);
    }
    __syncthreads();

    // layer 2: x = h @ W2 + b2   (3 groups of 128 outputs)
    #pragma unroll 1
    for (int g = 0; g < 3; g++) {
        float bb = b2[g * CC + d];
        uint64_t bi = pk(bb, bb);
        uint64_t a2[4];
        #pragma unroll
        for (int m = 0; m < 4; m++) a2[m] = bi;
        #pragma unroll 8
        for (int k = 0; k < CC; k++) {
            uint64_t ww = bcast2(W2[k * 3 * CC + g * CC + d]);
            const ulonglong2* row = reinterpret_cast<const ulonglong2*>(&shT[k * STR + h * NH]);
            ulonglong2 v0 = row[0], v1 = row[1];
            fma2(a2[0], v0.x, ww); fma2(a2[1], v0.y, ww);
            fma2(a2[2], v1.x, ww); fma2(a2[3], v1.y, ww);
        }
        #pragma unroll
        for (int m = 0; m < 4; m++) {
            float2 p = unpk(a2[m]);
            g_x[(base + h * NH + 2*m)     * 3 * CC + g * CC + d] = p.x;
            g_x[(base + h * NH + 2*m + 1) * 3 * CC + g * CC + d] = p.y;
        }
    }
}

// ============================================================================
// K2: edge kernel. One warp per 4 edges, Wf staged in smem, FFMA2 filter GEMV,
// gather x[j],mu[j] from L2, red.v4 scatter into g_q1/g_mu1.  (unchanged)
// ============================================================================
#define EPW 4
#define EWARPS 8

__global__ __launch_bounds__(256) void k_edge(
    const int*   __restrict__ eidx,     // [2,E]
    const float* __restrict__ ew,       // [E]
    const float* __restrict__ evs,      // [E,3]
    const float* __restrict__ attrs,    // [E,B]
    const float* __restrict__ Wf,       // [B,3C]
    const float* __restrict__ bf,       // [3C]
    const float* __restrict__ mu)       // [N,3,C]
{
    __shared__ __align__(16) float sWf[BB * 3 * CC];
    __shared__ __align__(16) float sbf[3 * CC];

    for (int t = threadIdx.x; t < BB * 3 * CC / 4; t += 256)
        reinterpret_cast<float4*>(sWf)[t] = reinterpret_cast<const float4*>(Wf)[t];
    for (int t = threadIdx.x; t < 3 * CC / 4; t += 256)
        reinterpret_cast<float4*>(sbf)[t] = reinterpret_cast<const float4*>(bf)[t];
    __syncthreads();

    const int lane  = threadIdx.x & 31;
    const int wid   = threadIdx.x >> 5;
    const int c0    = lane * 4;
    const int nwarp = gridDim.x * EWARPS;

    const float4 bq = *reinterpret_cast<const float4*>(&sbf[c0]);
    const float4 bR = *reinterpret_cast<const float4*>(&sbf[CC + c0]);
    const float4 bm = *reinterpret_cast<const float4*>(&sbf[2 * CC + c0]);

    for (int gidx = blockIdx.x * EWARPS + wid; gidx < EE / EPW; gidx += nwarp) {
        const int e0 = gidx * EPW;
        int ii[EPW], jj[EPW];
        float fc[EPW], av[EPW];
        #pragma unroll
        for (int t = 0; t < EPW; t++) {
            ii[t] = eidx[e0 + t];
            jj[t] = eidx[EE + e0 + t];
            float w = ew[e0 + t];
            fc[t] = (w < RCUT_F)
                ? 0.5f * (__cosf((3.14159265358979f / RCUT_F) * w) + 1.0f) : 0.0f;
            av[t] = (lane < BB) ? attrs[(e0 + t) * BB + lane] : 0.0f;
        }

        uint64_t acc[EPW][6];
        #pragma unroll
        for (int t = 0; t < EPW; t++) {
            acc[t][0] = pk(bq.x, bq.y); acc[t][1] = pk(bq.z, bq.w);
            acc[t][2] = pk(bR.x, bR.y); acc[t][3] = pk(bR.z, bR.w);
            acc[t][4] = pk(bm.x, bm.y); acc[t][5] = pk(bm.z, bm.w);
        }

        #pragma unroll
        for (int b = 0; b < BB; b++) {
            ulonglong2 f0 = *reinterpret_cast<const ulonglong2*>(&sWf[b * 3 * CC + c0]);
            ulonglong2 f1 = *reinterpret_cast<const ulonglong2*>(&sWf[b * 3 * CC + CC + c0]);
            ulonglong2 f2 = *reinterpret_cast<const ulonglong2*>(&sWf[b * 3 * CC + 2 * CC + c0]);
            #pragma unroll
            for (int t = 0; t < EPW; t++) {
                uint64_t aw = bcast2(__shfl_sync(0xFFFFFFFFu, av[t], b));
                fma2(acc[t][0], f0.x, aw); fma2(acc[t][1], f0.y, aw);
                fma2(acc[t][2], f1.x, aw); fma2(acc[t][3], f1.y, aw);
                fma2(acc[t][4], f2.x, aw); fma2(acc[t][5], f2.y, aw);
            }
        }

        #pragma unroll
        for (int t = 0; t < EPW; t++) {
            const int e = e0 + t;
            const float f = fc[t];
            const float ev0 = evs[e * 3 + 0];
            const float ev1 = evs[e * 3 + 1];
            const float ev2 = evs[e * 3 + 2];

            float2 wq0 = unpk(acc[t][0]), wq1 = unpk(acc[t][1]);
            float2 wR0 = unpk(acc[t][2]), wR1 = unpk(acc[t][3]);
            float2 wm0 = unpk(acc[t][4]), wm1 = unpk(acc[t][5]);

            const float4* xb = reinterpret_cast<const float4*>(&g_x[jj[t] * 3 * CC]);
            float4 x0 = xb[lane];
            float4 x1 = xb[32 + lane];
            float4 x2 = xb[64 + lane];

            float4 dq = make_float4(x0.x * wq0.x * f, x0.y * wq0.y * f,
                                    x0.z * wq1.x * f, x0.w * wq1.y * f);
            red4(&g_q1[ii[t] * CC + c0], dq);

            float4 cR = make_float4(x1.x * wR0.x * f, x1.y * wR0.y * f,
                                    x1.z * wR1.x * f, x1.w * wR1.y * f);
            float4 cm = make_float4(x2.x * wm0.x * f, x2.y * wm0.y * f,
                                    x2.z * wm1.x * f, x2.w * wm1.y * f);

            const float4* mub = reinterpret_cast<const float4*>(&mu[jj[t] * 3 * CC]);
            #pragma unroll
            for (int v = 0; v < 3; v++) {
                float evv = (v == 0) ? ev0 : (v == 1) ? ev1 : ev2;
                float4 mj = mub[v * 32 + lane];
                float4 dm = make_float4(fmaf(cm.x, mj.x, cR.x * evv),
                                        fmaf(cm.y, mj.y, cR.y * evv),
                                        fmaf(cm.z, mj.z, cR.z * evv),
                                        fmaf(cm.w, mj.w, cR.w * evv));
                red4(&g_mu1[(ii[t] * 3 + v) * CC + c0], dm);
            }
        }
    }
}

// ============================================================================
// K3a: mu_mix = mu1 @ W_mix -> muV, muW. mu1 treated as [3N,128].
// 16 rows/block, 256 threads (split-row halves).
// ============================================================================
__global__ __launch_bounds__(256) void k_mumix(const float* __restrict__ Wmix)
{
    __shared__ __align__(16) float sT[CC * STR];
    const int tid  = threadIdx.x;
    const int d    = tid & 127;
    const int h    = tid >> 7;
    const int base = blockIdx.x * NPB;

    #pragma unroll
    for (int n2 = 0; n2 < NH; n2++) {
        const int r = n2 * 2 + h;
        sT[d * STR + r] = g_mu1[(base + r) * CC + d];
    }
    __syncthreads();

    #pragma unroll 1
    for (int g = 0; g < 2; g++) {
        uint64_t acc[4];
        #pragma unroll
        for (int m = 0; m < 4; m++) acc[m] = 0ull;
        #pragma unroll 8
        for (int k = 0; k < CC; k++) {
            uint64_t ww = bcast2(Wmix[k * 2 * CC + g * CC + d]);
            const ulonglong2* row = reinterpret_cast<const ulonglong2*>(&sT[k * STR + h * NH]);
            ulonglong2 v0 = row[0], v1 = row[1];
            fma2(acc[0], v0.x, ww); fma2(acc[1], v0.y, ww);
            fma2(acc[2], v1.x, ww); fma2(acc[3], v1.y, ww);
        }
        float* dst = (g == 0) ? g_muV : g_muW;
        #pragma unroll
        for (int m = 0; m < 4; m++) {
            float2 p = unpk(acc[m]);
            dst[(base + h * NH + 2*m)     * CC + d] = p.x;
            dst[(base + h * NH + 2*m + 1) * CC + d] = p.y;
        }
    }
}

// ============================================================================
// K3b: mixing MLP + final outputs. 16 nodes/block, 256 threads.
// One smem buffer reused for ctx (256 rows) then hidden (128 rows).
// ============================================================================
__global__ __launch_bounds__(256) void k_mixout(
    const float* __restrict__ Wm1, const float* __restrict__ bm1,
    const float* __restrict__ Wm2, const float* __restrict__ bm2,
    float* __restrict__ out_q, float* __restrict__ out_mu)
{
    __shared__ __align__(16) float buf[2 * CC * STR];  // 20.5 KB; ctx then hidden
    const int tid  = threadIdx.x;
    const int d    = tid & 127;
    const int h    = tid >> 7;
    const int base = blockIdx.x * NPB;

    // transposed ctx tile: rows 0..127 = q1, rows 128..255 = |mu_V|
    #pragma unroll
    for (int n2 = 0; n2 < NH; n2++) {
        const int n = n2 * 2 + h;
        const int node = base + n;
        float q1v = g_q1[node * CC + d];
        float v0 = g_muV[(node * 3 + 0) * CC + d];
        float v1 = g_muV[(node * 3 + 1) * CC + d];
        float v2 = g_muV[(node * 3 + 2) * CC + d];
        float vn = sqrtf(fmaf(v0, v0, fmaf(v1, v1, fmaf(v2, v2, EPS_F))));
        buf[d * STR + n] = q1v;
        buf[(CC + d) * STR + n] = vn;
    }
    __syncthreads();

    // layer 1: hidden = silu(ctx @ Wm1 + bm1)
    uint64_t acc[4];
    {
        float bb = bm1[d];
        uint64_t bi = pk(bb, bb);
        #pragma unroll
        for (int m = 0; m < 4; m++) acc[m] = bi;
        #pragma unroll 8
        for (int k = 0; k < 2 * CC; k++) {
            uint64_t ww = bcast2(Wm1[k * CC + d]);
            const ulonglong2* row = reinterpret_cast<const ulonglong2*>(&buf[k * STR + h * NH]);
            ulonglong2 v0 = row[0], v1 = row[1];
            fma2(acc[0], v0.x, ww); fma2(acc[1], v0.y, ww);
            fma2(acc[2], v1.x, ww); fma2(acc[3], v1.y, ww);
        }
    }
    __syncthreads();   // all ctx reads done; reuse rows 0..127 for hidden
    #pragma unroll
    for (int m = 0; m < 4; m++) {
        float2 p = unpk(acc[m]);
        buf[d * STR + h * NH + 2*m]     = siluf(p.x);
        buf[d * STR + h * NH + 2*m + 1] = siluf(p.y);
    }
    __syncthreads();

    // layer 2 group-GEMV over hidden (rows 0..127)
    auto gemm_g = [&](int g, uint64_t* a) {
        float bb = bm2[g * CC + d];
        uint64_t bi = pk(bb, bb);
        #pragma unroll
        for (int m = 0; m < 4; m++) a[m] = bi;
        #pragma unroll 8
        for (int k = 0; k < CC; k++) {
            uint64_t ww = bcast2(Wm2[k * 3 * CC + g * CC + d]);
            const ulonglong2* row = reinterpret_cast<const ulonglong2*>(&buf[k * STR + h * NH]);
            ulonglong2 v0 = row[0], v1 = row[1];
            fma2(a[0], v0.x, ww); fma2(a[1], v0.y, ww);
            fma2(a[2], v1.x, ww); fma2(a[3], v1.y, ww);
        }
    };

    {
        uint64_t a2[4], a0[4];
        gemm_g(2, a2);      // dqmu_intra
        gemm_g(0, a0);      // dq_intra
        #pragma unroll
        for (int m = 0; m < 4; m++) {
            float2 p0 = unpk(a0[m]);
            float2 p2 = unpk(a2[m]);
            #pragma unroll
            for (int t = 0; t < 2; t++) {
                const int node = base + h * NH + 2*m + t;
                float v0 = g_muV[(node * 3 + 0) * CC + d];
                float v1 = g_muV[(node * 3 + 1) * CC + d];
                float v2 = g_muV[(node * 3 + 2) * CC + d];
                float w0 = g_muW[(node * 3 + 0) * CC + d];
                float w1 = g_muW[(node * 3 + 1) * CC + d];
                float w2 = g_muW[(node * 3 + 2) * CC + d];
                float scal = fmaf(v0, w0, fmaf(v1, w1, v2 * w2));
                float q1v  = g_q1[node * CC + d];
                float y0 = t ? p0.y : p0.x;
                float y2 = t ? p2.y : p2.x;
                out_q[node * CC + d] = q1v + y0 + y2 * scal;
            }
        }
    }
    {
        uint64_t a1[4];
        gemm_g(1, a1);      // dmu_intra
        #pragma unroll
        for (int m = 0; m < 4; m++) {
            float2 p1 = unpk(a1[m]);
            #pragma unroll
            for (int t = 0; t < 2; t++) {
                const int node = base + h * NH + 2*m + t;
                float y1 = t ? p1.y : p1.x;
                #pragma unroll
                for (int v = 0; v < 3; v++) {
                    float mw = g_muW[(node * 3 + v) * CC + d];
                    float m1 = g_mu1[(node * 3 + v) * CC + d];
                    out_mu[(node * 3 + v) * CC + d] = fmaf(y1, mw, m1);
                }
            }
        }
    }
}

// ============================================================================
extern "C" void kernel_launch(void* const* d_in, const int* in_sizes, int n_in,
                              void* d_out, int out_size)
{
    const float* q     = (const float*)d_in[0];
    const float* mu    = (const float*)d_in[1];
    const int*   eidx  = (const int*)  d_in[2];
    const float* ew    = (const float*)d_in[3];
    const float* evs   = (const float*)d_in[4];
    const float* attrs = (const float*)d_in[5];
    const float* Wf    = (const float*)d_in[6];
    const float* bf    = (const float*)d_in[7];
    const float* W1    = (const float*)d_in[8];
    const float* b1    = (const float*)d_in[9];
    const float* W2    = (const float*)d_in[10];
    const float* b2    = (const float*)d_in[11];
    const float* Wmix  = (const float*)d_in[12];
    const float* Wm1   = (const float*)d_in[13];
    const float* bm1   = (const float*)d_in[14];
    const float* Wm2   = (const float*)d_in[15];
    const float* bm2   = (const float*)d_in[16];

    float* out_q  = (float*)d_out;
    float* out_mu = out_q + (size_t)NN * CC;

    k_context<<<NN / NPB, 256>>>(q, mu, W1, b1, W2, b2);
    k_edge<<<1184, 256>>>(eidx, ew, evs, attrs, Wf, bf, mu);
    k_mumix<<<(3 * NN) / NPB, 256>>>(Wmix);
    k_mixout<<<NN / NPB, 256>>>(Wm1, bm1, Wm2, bm2, out_q, out_mu);
}

// round 10
// speedup vs baseline: 1.7634x; 1.2763x over previous
#include <cuda_runtime.h>
#include <cstdint>

#define NN 20000
#define EE 320000
#define CC 128
#define BB 20
#define RCUT_F 5.0f
#define EPS_F 1e-8f

// ---------------- scratch (device globals; no allocation allowed) ----------------
__device__ float g_x  [NN * 3 * CC];   // per-node context net output [N,3C]
__device__ float g_q1 [NN * CC];       // q + dq (accumulated)
__device__ float g_mu1[NN * 3 * CC];   // mu + dmu (accumulated)
__device__ float g_muV[NN * 3 * CC];
__device__ float g_muW[NN * 3 * CC];

// ---------------- helpers ----------------
__device__ __forceinline__ void red4(float* p, float4 v) {
    asm volatile("red.global.add.v4.f32 [%0], {%1,%2,%3,%4};"
                 :: "l"(p), "f"(v.x), "f"(v.y), "f"(v.z), "f"(v.w) : "memory");
}
__device__ __forceinline__ float siluf(float x) {
    return x * (1.0f / (1.0f + __expf(-x)));
}
// packed fp32x2 FMA (Blackwell FFMA2): d = a*b + d
__device__ __forceinline__ void fma2(uint64_t& d, uint64_t a, uint64_t b) {
    asm("fma.rn.f32x2 %0, %1, %2, %0;" : "+l"(d) : "l"(a), "l"(b));
}
__device__ __forceinline__ uint64_t pk(float lo, float hi) {
    uint64_t r; asm("mov.b64 %0, {%1, %2};" : "=l"(r) : "f"(lo), "f"(hi)); return r;
}
__device__ __forceinline__ uint64_t bcast2(float w) {
    uint64_t r; asm("mov.b64 %0, {%1, %1};" : "=l"(r) : "f"(w)); return r;
}
__device__ __forceinline__ float2 unpk(uint64_t p) {
    float2 r; asm("mov.b64 {%0, %1}, %2;" : "=f"(r.x), "=f"(r.y) : "l"(p)); return r;
}

// Node-GEMV tiling: 256 threads, 16 nodes/block.
// thread = (d = tid&127 output channel, h = tid>>7 node-half); each half owns 8 nodes.
#define NPB 16
#define NH  8
#define STR 20   // padded tile row stride in floats (80B; 16B-aligned subrows)

// ============================================================================
// K1: context net  x = silu(q@W1+b1)@W2+b2 ; seed g_q1=q, g_mu1=mu
// ============================================================================
__global__ __launch_bounds__(256) void k_context(
    const float* __restrict__ q, const float* __restrict__ mu,
    const float* __restrict__ W1, const float* __restrict__ b1,
    const float* __restrict__ W2, const float* __restrict__ b2)
{
    __shared__ __align__(16) float sqT[CC * STR];   // [k][n]
    __shared__ __align__(16) float shT[CC * STR];   // [k][n]
    const int tid  = threadIdx.x;
    const int d    = tid & 127;
    const int h    = tid >> 7;
    const int base = blockIdx.x * NPB;

    // load q rows (coalesced over d) into transposed tile; seed g_q1
    #pragma unroll
    for (int n2 = 0; n2 < NH; n2++) {
        const int n = n2 * 2 + h;
        float v = q[(base + n) * CC + d];
        sqT[d * STR + n] = v;
        g_q1[(base + n) * CC + d] = v;
    }
    // seed g_mu1 = mu
    {
        const float4* src = reinterpret_cast<const float4*>(&mu[base * 3 * CC]);
        float4* dst = reinterpret_cast<float4*>(&g_mu1[base * 3 * CC]);
        #pragma unroll
        for (int t = tid; t < NPB * 3 * CC / 4; t += 256) dst[t] = src[t];
    }
    __syncthreads();

    // layer 1: h = silu(q @ W1 + b1)
    uint64_t acc[4];
    {
        float bb = b1[d];
        uint64_t bi = pk(bb, bb);
        #pragma unroll
        for (int m = 0; m < 4; m++) acc[m] = bi;
        #pragma unroll 16
        for (int k = 0; k < CC; k++) {
            uint64_t ww = bcast2(W1[k * CC + d]);
            const ulonglong2* row = reinterpret_cast<const ulonglong2*>(&sqT[k * STR + h * NH]);
            ulonglong2 v0 = row[0], v1 = row[1];
            fma2(acc[0], v0.x, ww); fma2(acc[1], v0.y, ww);
            fma2(acc[2], v1.x, ww); fma2(acc[3], v1.y, ww);
        }
    }
    #pragma unroll
    for (int m = 0; m < 4; m++) {
        float2 p = unpk(acc[m]);
        shT[d * STR + h * NH + 2*m]     = siluf(p.x);
        shT[d * STR + h * NH + 2*m + 1] = siluf(p.y);
    }
    __syncthreads();

    // layer 2: x = h @ W2 + b2 — 3 output groups fused into ONE k-pass
    {
        uint64_t a2[3][4];
        #pragma unroll
        for (int g = 0; g < 3; g++) {
            float bb = b2[g * CC + d];
            uint64_t bi = pk(bb, bb);
            #pragma unroll
            for (int m = 0; m < 4; m++) a2[g][m] = bi;
        }
        #pragma unroll 8
        for (int k = 0; k < CC; k++) {
            uint64_t w0 = bcast2(W2[k * 3 * CC + 0 * CC + d]);
            uint64_t w1 = bcast2(W2[k * 3 * CC + 1 * CC + d]);
            uint64_t w2 = bcast2(W2[k * 3 * CC + 2 * CC + d]);
            const ulonglong2* row = reinterpret_cast<const ulonglong2*>(&shT[k * STR + h * NH]);
            ulonglong2 v0 = row[0], v1 = row[1];
            fma2(a2[0][0], v0.x, w0); fma2(a2[0][1], v0.y, w0);
            fma2(a2[0][2], v1.x, w0); fma2(a2[0][3], v1.y, w0);
            fma2(a2[1][0], v0.x, w1); fma2(a2[1][1], v0.y, w1);
            fma2(a2[1][2], v1.x, w1); fma2(a2[1][3], v1.y, w1);
            fma2(a2[2][0], v0.x, w2); fma2(a2[2][1], v0.y, w2);
            fma2(a2[2][2], v1.x, w2); fma2(a2[2][3], v1.y, w2);
        }
        #pragma unroll
        for (int g = 0; g < 3; g++) {
            #pragma unroll
            for (int m = 0; m < 4; m++) {
                float2 p = unpk(a2[g][m]);
                g_x[(base + h * NH + 2*m)     * 3 * CC + g * CC + d] = p.x;
                g_x[(base + h * NH + 2*m + 1) * 3 * CC + g * CC + d] = p.y;
            }
        }
    }
}

// ============================================================================
// K2: edge kernel. One warp per 4 edges, Wf staged in smem, FFMA2 filter GEMV,
// gather x[j],mu[j] from L2, red.v4 scatter into g_q1/g_mu1.  (unchanged)
// ============================================================================
#define EPW 4
#define EWARPS 8

__global__ __launch_bounds__(256) void k_edge(
    const int*   __restrict__ eidx,     // [2,E]
    const float* __restrict__ ew,       // [E]
    const float* __restrict__ evs,      // [E,3]
    const float* __restrict__ attrs,    // [E,B]
    const float* __restrict__ Wf,       // [B,3C]
    const float* __restrict__ bf,       // [3C]
    const float* __restrict__ mu)       // [N,3,C]
{
    __shared__ __align__(16) float sWf[BB * 3 * CC];
    __shared__ __align__(16) float sbf[3 * CC];

    for (int t = threadIdx.x; t < BB * 3 * CC / 4; t += 256)
        reinterpret_cast<float4*>(sWf)[t] = reinterpret_cast<const float4*>(Wf)[t];
    for (int t = threadIdx.x; t < 3 * CC / 4; t += 256)
        reinterpret_cast<float4*>(sbf)[t] = reinterpret_cast<const float4*>(bf)[t];
    __syncthreads();

    const int lane  = threadIdx.x & 31;
    const int wid   = threadIdx.x >> 5;
    const int c0    = lane * 4;
    const int nwarp = gridDim.x * EWARPS;

    const float4 bq = *reinterpret_cast<const float4*>(&sbf[c0]);
    const float4 bR = *reinterpret_cast<const float4*>(&sbf[CC + c0]);
    const float4 bm = *reinterpret_cast<const float4*>(&sbf[2 * CC + c0]);

    for (int gidx = blockIdx.x * EWARPS + wid; gidx < EE / EPW; gidx += nwarp) {
        const int e0 = gidx * EPW;
        int ii[EPW], jj[EPW];
        float fc[EPW], av[EPW];
        #pragma unroll
        for (int t = 0; t < EPW; t++) {
            ii[t] = eidx[e0 + t];
            jj[t] = eidx[EE + e0 + t];
            float w = ew[e0 + t];
            fc[t] = (w < RCUT_F)
                ? 0.5f * (__cosf((3.14159265358979f / RCUT_F) * w) + 1.0f) : 0.0f;
            av[t] = (lane < BB) ? attrs[(e0 + t) * BB + lane] : 0.0f;
        }

        uint64_t acc[EPW][6];
        #pragma unroll
        for (int t = 0; t < EPW; t++) {
            acc[t][0] = pk(bq.x, bq.y); acc[t][1] = pk(bq.z, bq.w);
            acc[t][2] = pk(bR.x, bR.y); acc[t][3] = pk(bR.z, bR.w);
            acc[t][4] = pk(bm.x, bm.y); acc[t][5] = pk(bm.z, bm.w);
        }

        #pragma unroll
        for (int b = 0; b < BB; b++) {
            ulonglong2 f0 = *reinterpret_cast<const ulonglong2*>(&sWf[b * 3 * CC + c0]);
            ulonglong2 f1 = *reinterpret_cast<const ulonglong2*>(&sWf[b * 3 * CC + CC + c0]);
            ulonglong2 f2 = *reinterpret_cast<const ulonglong2*>(&sWf[b * 3 * CC + 2 * CC + c0]);
            #pragma unroll
            for (int t = 0; t < EPW; t++) {
                uint64_t aw = bcast2(__shfl_sync(0xFFFFFFFFu, av[t], b));
                fma2(acc[t][0], f0.x, aw); fma2(acc[t][1], f0.y, aw);
                fma2(acc[t][2], f1.x, aw); fma2(acc[t][3], f1.y, aw);
                fma2(acc[t][4], f2.x, aw); fma2(acc[t][5], f2.y, aw);
            }
        }

        #pragma unroll
        for (int t = 0; t < EPW; t++) {
            const int e = e0 + t;
            const float f = fc[t];
            const float ev0 = evs[e * 3 + 0];
            const float ev1 = evs[e * 3 + 1];
            const float ev2 = evs[e * 3 + 2];

            float2 wq0 = unpk(acc[t][0]), wq1 = unpk(acc[t][1]);
            float2 wR0 = unpk(acc[t][2]), wR1 = unpk(acc[t][3]);
            float2 wm0 = unpk(acc[t][4]), wm1 = unpk(acc[t][5]);

            const float4* xb = reinterpret_cast<const float4*>(&g_x[jj[t] * 3 * CC]);
            float4 x0 = xb[lane];
            float4 x1 = xb[32 + lane];
            float4 x2 = xb[64 + lane];

            float4 dq = make_float4(x0.x * wq0.x * f, x0.y * wq0.y * f,
                                    x0.z * wq1.x * f, x0.w * wq1.y * f);
            red4(&g_q1[ii[t] * CC + c0], dq);

            float4 cR = make_float4(x1.x * wR0.x * f, x1.y * wR0.y * f,
                                    x1.z * wR1.x * f, x1.w * wR1.y * f);
            float4 cm = make_float4(x2.x * wm0.x * f, x2.y * wm0.y * f,
                                    x2.z * wm1.x * f, x2.w * wm1.y * f);

            const float4* mub = reinterpret_cast<const float4*>(&mu[jj[t] * 3 * CC]);
            #pragma unroll
            for (int v = 0; v < 3; v++) {
                float evv = (v == 0) ? ev0 : (v == 1) ? ev1 : ev2;
                float4 mj = mub[v * 32 + lane];
                float4 dm = make_float4(fmaf(cm.x, mj.x, cR.x * evv),
                                        fmaf(cm.y, mj.y, cR.y * evv),
                                        fmaf(cm.z, mj.z, cR.z * evv),
                                        fmaf(cm.w, mj.w, cR.w * evv));
                red4(&g_mu1[(ii[t] * 3 + v) * CC + c0], dm);
            }
        }
    }
}

// ============================================================================
// K3a: mu_mix = mu1 @ W_mix -> muV, muW. mu1 treated as [3N,128].
// 16 rows/block, 256 threads; BOTH output groups fused into one k-pass.
// ============================================================================
__global__ __launch_bounds__(256) void k_mumix(const float* __restrict__ Wmix)
{
    __shared__ __align__(16) float sT[CC * STR];
    const int tid  = threadIdx.x;
    const int d    = tid & 127;
    const int h    = tid >> 7;
    const int base = blockIdx.x * NPB;

    #pragma unroll
    for (int n2 = 0; n2 < NH; n2++) {
        const int r = n2 * 2 + h;
        sT[d * STR + r] = g_mu1[(base + r) * CC + d];
    }
    __syncthreads();

    uint64_t acc[2][4];
    #pragma unroll
    for (int g = 0; g < 2; g++)
        #pragma unroll
        for (int m = 0; m < 4; m++) acc[g][m] = 0ull;

    #pragma unroll 8
    for (int k = 0; k < CC; k++) {
        uint64_t w0 = bcast2(Wmix[k * 2 * CC + 0 * CC + d]);
        uint64_t w1 = bcast2(Wmix[k * 2 * CC + 1 * CC + d]);
        const ulonglong2* row = reinterpret_cast<const ulonglong2*>(&sT[k * STR + h * NH]);
        ulonglong2 v0 = row[0], v1 = row[1];
        fma2(acc[0][0], v0.x, w0); fma2(acc[0][1], v0.y, w0);
        fma2(acc[0][2], v1.x, w0); fma2(acc[0][3], v1.y, w0);
        fma2(acc[1][0], v0.x, w1); fma2(acc[1][1], v0.y, w1);
        fma2(acc[1][2], v1.x, w1); fma2(acc[1][3], v1.y, w1);
    }
    #pragma unroll
    for (int g = 0; g < 2; g++) {
        float* dst = (g == 0) ? g_muV : g_muW;
        #pragma unroll
        for (int m = 0; m < 4; m++) {
            float2 p = unpk(acc[g][m]);
            dst[(base + h * NH + 2*m)     * CC + d] = p.x;
            dst[(base + h * NH + 2*m + 1) * CC + d] = p.y;
        }
    }
}

// ============================================================================
// K3b: mixing MLP + final outputs. 16 nodes/block, 256 threads.
// ctx rows 0..127 = q1 (preserved for epilogue), rows 128..255 = |mu_V| then
// overwritten by hidden. scal precomputed into smem. Layer2: 3 groups fused.
// ============================================================================
__global__ __launch_bounds__(256) void k_mixout(
    const float* __restrict__ Wm1, const float* __restrict__ bm1,
    const float* __restrict__ Wm2, const float* __restrict__ bm2,
    float* __restrict__ out_q, float* __restrict__ out_mu)
{
    __shared__ __align__(16) float buf[2 * CC * STR];   // 20.5 KB
    __shared__ __align__(16) float sscal[NPB * CC];     //  8 KB
    const int tid  = threadIdx.x;
    const int d    = tid & 127;
    const int h    = tid >> 7;
    const int base = blockIdx.x * NPB;

    // prologue: ctx tile (q1, |mu_V|) + scal = <mu_V, mu_W> per (node,d)
    #pragma unroll
    for (int n2 = 0; n2 < NH; n2++) {
        const int n = n2 * 2 + h;
        const int node = base + n;
        float q1v = g_q1[node * CC + d];
        float v0 = g_muV[(node * 3 + 0) * CC + d];
        float v1 = g_muV[(node * 3 + 1) * CC + d];
        float v2 = g_muV[(node * 3 + 2) * CC + d];
        float w0 = g_muW[(node * 3 + 0) * CC + d];
        float w1 = g_muW[(node * 3 + 1) * CC + d];
        float w2 = g_muW[(node * 3 + 2) * CC + d];
        float vn = sqrtf(fmaf(v0, v0, fmaf(v1, v1, fmaf(v2, v2, EPS_F))));
        sscal[n * CC + d] = fmaf(v0, w0, fmaf(v1, w1, v2 * w2));
        buf[d * STR + n] = q1v;
        buf[(CC + d) * STR + n] = vn;
    }
    __syncthreads();

    // layer 1: hidden = silu(ctx @ Wm1 + bm1)
    uint64_t acc[4];
    {
        float bb = bm1[d];
        uint64_t bi = pk(bb, bb);
        #pragma unroll
        for (int m = 0; m < 4; m++) acc[m] = bi;
        #pragma unroll 16
        for (int k = 0; k < 2 * CC; k++) {
            uint64_t ww = bcast2(Wm1[k * CC + d]);
            const ulonglong2* row = reinterpret_cast<const ulonglong2*>(&buf[k * STR + h * NH]);
            ulonglong2 v0 = row[0], v1 = row[1];
            fma2(acc[0], v0.x, ww); fma2(acc[1], v0.y, ww);
            fma2(acc[2], v1.x, ww); fma2(acc[3], v1.y, ww);
        }
    }
    __syncthreads();   // all ctx reads done; overwrite vn rows (128..255) w/ hidden
    #pragma unroll
    for (int m = 0; m < 4; m++) {
        float2 p = unpk(acc[m]);
        buf[(CC + d) * STR + h * NH + 2*m]     = siluf(p.x);
        buf[(CC + d) * STR + h * NH + 2*m + 1] = siluf(p.y);
    }
    __syncthreads();

    // layer 2: all 3 output groups fused into one k-pass over hidden
    uint64_t a[3][4];
    #pragma unroll
    for (int g = 0; g < 3; g++) {
        float bb = bm2[g * CC + d];
        uint64_t bi = pk(bb, bb);
        #pragma unroll
        for (int m = 0; m < 4; m++) a[g][m] = bi;
    }
    #pragma unroll 8
    for (int k = 0; k < CC; k++) {
        uint64_t w0 = bcast2(Wm2[k * 3 * CC + 0 * CC + d]);
        uint64_t w1 = bcast2(Wm2[k * 3 * CC + 1 * CC + d]);
        uint64_t w2 = bcast2(Wm2[k * 3 * CC + 2 * CC + d]);
        const ulonglong2* row = reinterpret_cast<const ulonglong2*>(&buf[(CC + k) * STR + h * NH]);
        ulonglong2 v0 = row[0], v1 = row[1];
        fma2(a[0][0], v0.x, w0); fma2(a[0][1], v0.y, w0);
        fma2(a[0][2], v1.x, w0); fma2(a[0][3], v1.y, w0);
        fma2(a[1][0], v0.x, w1); fma2(a[1][1], v0.y, w1);
        fma2(a[1][2], v1.x, w1); fma2(a[1][3], v1.y, w1);
        fma2(a[2][0], v0.x, w2); fma2(a[2][1], v0.y, w2);
        fma2(a[2][2], v1.x, w2); fma2(a[2][3], v1.y, w2);
    }

    // epilogue
    #pragma unroll
    for (int m = 0; m < 4; m++) {
        float2 p0 = unpk(a[0][m]);   // dq_intra
        float2 p1 = unpk(a[1][m]);   // dmu_intra
        float2 p2 = unpk(a[2][m]);   // dqmu_intra
        #pragma unroll
        for (int t = 0; t < 2; t++) {
            const int n = h * NH + 2*m + t;
            const int node = base + n;
            float y0 = t ? p0.y : p0.x;
            float y1 = t ? p1.y : p1.x;
            float y2 = t ? p2.y : p2.x;
            float q1v  = buf[d * STR + n];          // preserved ctx row
            float scal = sscal[n * CC + d];
            out_q[node * CC + d] = q1v + y0 + y2 * scal;
            #pragma unroll
            for (int v = 0; v < 3; v++) {
                float mw = g_muW[(node * 3 + v) * CC + d];
                float m1 = g_mu1[(node * 3 + v) * CC + d];
                out_mu[(node * 3 + v) * CC + d] = fmaf(y1, mw, m1);
            }
        }
    }
}

// ============================================================================
extern "C" void kernel_launch(void* const* d_in, const int* in_sizes, int n_in,
                              void* d_out, int out_size)
{
    const float* q     = (const float*)d_in[0];
    const float* mu    = (const float*)d_in[1];
    const int*   eidx  = (const int*)  d_in[2];
    const float* ew    = (const float*)d_in[3];
    const float* evs   = (const float*)d_in[4];
    const float* attrs = (const float*)d_in[5];
    const float* Wf    = (const float*)d_in[6];
    const float* bf    = (const float*)d_in[7];
    const float* W1    = (const float*)d_in[8];
    const float* b1    = (const float*)d_in[9];
    const float* W2    = (const float*)d_in[10];
    const float* b2    = (const float*)d_in[11];
    const float* Wmix  = (const float*)d_in[12];
    const float* Wm1   = (const float*)d_in[13];
    const float* bm1   = (const float*)d_in[14];
    const float* Wm2   = (const float*)d_in[15];
    const float* bm2   = (const float*)d_in[16];

    float* out_q  = (float*)d_out;
    float* out_mu = out_q + (size_t)NN * CC;

    k_context<<<NN / NPB, 256>>>(q, mu, W1, b1, W2, b2);
    k_edge<<<1184, 256>>>(eidx, ew, evs, attrs, Wf, bf, mu);
    k_mumix<<<(3 * NN) / NPB, 256>>>(Wmix);
    k_mixout<<<NN / NPB, 256>>>(Wm1, bm1, Wm2, bm2, out_q, out_mu);
}

// round 11
// speedup vs baseline: 1.8493x; 1.0487x over previous
#include <cuda_runtime.h>
#include <cstdint>

#define NN 20000
#define EE 320000
#define CC 128
#define BB 20
#define RCUT_F 5.0f
#define EPS_F 1e-8f

// ---------------- scratch (device globals; no allocation allowed) ----------------
__device__ float g_x  [NN * 3 * CC];   // per-node context net output [N,3C]
__device__ float g_q1 [NN * CC];       // q + dq (accumulated)
__device__ float g_mu1[NN * 3 * CC];   // mu + dmu (accumulated)
__device__ float g_muV[NN * 3 * CC];
__device__ float g_muW[NN * 3 * CC];

// ---------------- helpers ----------------
__device__ __forceinline__ void red4(float* p, float4 v) {
    asm volatile("red.global.add.v4.f32 [%0], {%1,%2,%3,%4};"
                 :: "l"(p), "f"(v.x), "f"(v.y), "f"(v.z), "f"(v.w) : "memory");
}
__device__ __forceinline__ float siluf(float x) {
    return x * (1.0f / (1.0f + __expf(-x)));
}
// packed fp32x2 FMA (Blackwell FFMA2): d = a*b + d
__device__ __forceinline__ void fma2(uint64_t& d, uint64_t a, uint64_t b) {
    asm("fma.rn.f32x2 %0, %1, %2, %0;" : "+l"(d) : "l"(a), "l"(b));
}
__device__ __forceinline__ uint64_t pk(float lo, float hi) {
    uint64_t r; asm("mov.b64 %0, {%1, %2};" : "=l"(r) : "f"(lo), "f"(hi)); return r;
}
__device__ __forceinline__ uint64_t bcast2(float w) {
    uint64_t r; asm("mov.b64 %0, {%1, %1};" : "=l"(r) : "f"(w)); return r;
}
__device__ __forceinline__ float2 unpk(uint64_t p) {
    float2 r; asm("mov.b64 {%0, %1}, %2;" : "=f"(r.x), "=f"(r.y) : "l"(p)); return r;
}
// cp.async (LDGSTS): zero-register weight staging
__device__ __forceinline__ void cpa16(uint32_t dst, const float* src) {
    asm volatile("cp.async.cg.shared.global [%0], [%1], 16;" :: "r"(dst), "l"(src));
}
#define CP_COMMIT() asm volatile("cp.async.commit_group;" ::: "memory")
#define CP_WAIT0()  asm volatile("cp.async.wait_group 0;" ::: "memory")

// Node-GEMV tiling: 256 threads, 16 nodes/block.
// thread = (d = tid&127 output channel, h = tid>>7 node-half); each half owns 8 nodes.
#define NPB 16
#define NH  8
#define STR 20   // padded tile row stride in floats

// ============================================================================
// K1: context net  x = silu(q@W1+b1)@W2+b2 ; seed g_q1=q, g_mu1=mu
// Weights double-buffered through smem via cp.async.
// ============================================================================
#define K1R1 16            // k-rows/tile, layer1 (W1: [128][128])
#define K1T1 (CC / K1R1)   // 8 tiles
#define K1R2 8             // k-rows/tile, layer2 (W2: [128][384])
#define K1T2 (CC / K1R2)   // 16 tiles

__global__ __launch_bounds__(256) void k_context(
    const float* __restrict__ q, const float* __restrict__ mu,
    const float* __restrict__ W1, const float* __restrict__ b1,
    const float* __restrict__ W2, const float* __restrict__ b2)
{
    __shared__ __align__(16) float sqT[CC * STR];       // [k][n]
    __shared__ __align__(16) float shT[CC * STR];       // [k][n]
    __shared__ __align__(16) float sW[2][3 * CC * K1R2]; // 2 x 3072 floats (24 KB)
    const int tid  = threadIdx.x;
    const int d    = tid & 127;
    const int h    = tid >> 7;
    const int base = blockIdx.x * NPB;
    const uint32_t swb0 = (uint32_t)__cvta_generic_to_shared(sW[0]);
    const uint32_t swb1 = (uint32_t)__cvta_generic_to_shared(sW[1]);

    #pragma unroll
    for (int n2 = 0; n2 < NH; n2++) {
        const int n = n2 * 2 + h;
        float v = q[(base + n) * CC + d];
        sqT[d * STR + n] = v;
        g_q1[(base + n) * CC + d] = v;
    }
    {
        const float4* src = reinterpret_cast<const float4*>(&mu[base * 3 * CC]);
        float4* dst = reinterpret_cast<float4*>(&g_mu1[base * 3 * CC]);
        #pragma unroll
        for (int t = tid; t < NPB * 3 * CC / 4; t += 256) dst[t] = src[t];
    }
    __syncthreads();

    // ---- layer 1: h = silu(q @ W1 + b1), tiles of K1R1 rows ----
    uint64_t acc[4];
    {
        float bb = b1[d];
        uint64_t bi = pk(bb, bb);
        #pragma unroll
        for (int m = 0; m < 4; m++) acc[m] = bi;

        #pragma unroll
        for (int t = tid; t < K1R1 * CC / 4; t += 256)
            cpa16(swb0 + t * 16, W1 + t * 4);
        CP_COMMIT();

        for (int kt = 0; kt < K1T1; kt++) {
            CP_WAIT0();
            __syncthreads();
            if (kt + 1 < K1T1) {
                const float* src = W1 + (kt + 1) * K1R1 * CC;
                uint32_t dstb = ((kt + 1) & 1) ? swb1 : swb0;
                #pragma unroll
                for (int t = tid; t < K1R1 * CC / 4; t += 256)
                    cpa16(dstb + t * 16, src + t * 4);
                CP_COMMIT();
            }
            const float* sWt = sW[kt & 1];
            #pragma unroll
            for (int r = 0; r < K1R1; r++) {
                const int k = kt * K1R1 + r;
                uint64_t ww = bcast2(sWt[r * CC + d]);
                const ulonglong2* row = reinterpret_cast<const ulonglong2*>(&sqT[k * STR + h * NH]);
                ulonglong2 v0 = row[0], v1 = row[1];
                fma2(acc[0], v0.x, ww); fma2(acc[1], v0.y, ww);
                fma2(acc[2], v1.x, ww); fma2(acc[3], v1.y, ww);
            }
        }
    }
    __syncthreads();
    #pragma unroll
    for (int m = 0; m < 4; m++) {
        float2 p = unpk(acc[m]);
        shT[d * STR + h * NH + 2*m]     = siluf(p.x);
        shT[d * STR + h * NH + 2*m + 1] = siluf(p.y);
    }
    __syncthreads();

    // ---- layer 2: x = h @ W2 + b2, 3 groups fused, tiles of K1R2 rows ----
    {
        uint64_t a2[3][4];
        #pragma unroll
        for (int g = 0; g < 3; g++) {
            float bb = b2[g * CC + d];
            uint64_t bi = pk(bb, bb);
            #pragma unroll
            for (int m = 0; m < 4; m++) a2[g][m] = bi;
        }
        #pragma unroll
        for (int t = tid; t < K1R2 * 3 * CC / 4; t += 256)
            cpa16(swb0 + t * 16, W2 + t * 4);
        CP_COMMIT();

        for (int kt = 0; kt < K1T2; kt++) {
            CP_WAIT0();
            __syncthreads();
            if (kt + 1 < K1T2) {
                const float* src = W2 + (kt + 1) * K1R2 * 3 * CC;
                uint32_t dstb = ((kt + 1) & 1) ? swb1 : swb0;
                #pragma unroll
                for (int t = tid; t < K1R2 * 3 * CC / 4; t += 256)
                    cpa16(dstb + t * 16, src + t * 4);
                CP_COMMIT();
            }
            const float* sWt = sW[kt & 1];
            #pragma unroll
            for (int r = 0; r < K1R2; r++) {
                const int k = kt * K1R2 + r;
                uint64_t w0 = bcast2(sWt[r * 3 * CC + 0 * CC + d]);
                uint64_t w1 = bcast2(sWt[r * 3 * CC + 1 * CC + d]);
                uint64_t w2 = bcast2(sWt[r * 3 * CC + 2 * CC + d]);
                const ulonglong2* row = reinterpret_cast<const ulonglong2*>(&shT[k * STR + h * NH]);
                ulonglong2 v0 = row[0], v1 = row[1];
                fma2(a2[0][0], v0.x, w0); fma2(a2[0][1], v0.y, w0);
                fma2(a2[0][2], v1.x, w0); fma2(a2[0][3], v1.y, w0);
                fma2(a2[1][0], v0.x, w1); fma2(a2[1][1], v0.y, w1);
                fma2(a2[1][2], v1.x, w1); fma2(a2[1][3], v1.y, w1);
                fma2(a2[2][0], v0.x, w2); fma2(a2[2][1], v0.y, w2);
                fma2(a2[2][2], v1.x, w2); fma2(a2[2][3], v1.y, w2);
            }
        }
        #pragma unroll
        for (int g = 0; g < 3; g++) {
            #pragma unroll
            for (int m = 0; m < 4; m++) {
                float2 p = unpk(a2[g][m]);
                g_x[(base + h * NH + 2*m)     * 3 * CC + g * CC + d] = p.x;
                g_x[(base + h * NH + 2*m + 1) * 3 * CC + g * CC + d] = p.y;
            }
        }
    }
}

// ============================================================================
// K2: edge kernel. One warp per 4 edges, Wf staged in smem, FFMA2 filter GEMV,
// gather x[j],mu[j] from L2, red.v4 scatter into g_q1/g_mu1.  (unchanged)
// ============================================================================
#define EPW 4
#define EWARPS 8

__global__ __launch_bounds__(256) void k_edge(
    const int*   __restrict__ eidx,     // [2,E]
    const float* __restrict__ ew,       // [E]
    const float* __restrict__ evs,      // [E,3]
    const float* __restrict__ attrs,    // [E,B]
    const float* __restrict__ Wf,       // [B,3C]
    const float* __restrict__ bf,       // [3C]
    const float* __restrict__ mu)       // [N,3,C]
{
    __shared__ __align__(16) float sWf[BB * 3 * CC];
    __shared__ __align__(16) float sbf[3 * CC];

    for (int t = threadIdx.x; t < BB * 3 * CC / 4; t += 256)
        reinterpret_cast<float4*>(sWf)[t] = reinterpret_cast<const float4*>(Wf)[t];
    for (int t = threadIdx.x; t < 3 * CC / 4; t += 256)
        reinterpret_cast<float4*>(sbf)[t] = reinterpret_cast<const float4*>(bf)[t];
    __syncthreads();

    const int lane  = threadIdx.x & 31;
    const int wid   = threadIdx.x >> 5;
    const int c0    = lane * 4;
    const int nwarp = gridDim.x * EWARPS;

    const float4 bq = *reinterpret_cast<const float4*>(&sbf[c0]);
    const float4 bR = *reinterpret_cast<const float4*>(&sbf[CC + c0]);
    const float4 bm = *reinterpret_cast<const float4*>(&sbf[2 * CC + c0]);

    for (int gidx = blockIdx.x * EWARPS + wid; gidx < EE / EPW; gidx += nwarp) {
        const int e0 = gidx * EPW;
        int ii[EPW], jj[EPW];
        float fc[EPW], av[EPW];
        #pragma unroll
        for (int t = 0; t < EPW; t++) {
            ii[t] = eidx[e0 + t];
            jj[t] = eidx[EE + e0 + t];
            float w = ew[e0 + t];
            fc[t] = (w < RCUT_F)
                ? 0.5f * (__cosf((3.14159265358979f / RCUT_F) * w) + 1.0f) : 0.0f;
            av[t] = (lane < BB) ? attrs[(e0 + t) * BB + lane] : 0.0f;
        }

        uint64_t acc[EPW][6];
        #pragma unroll
        for (int t = 0; t < EPW; t++) {
            acc[t][0] = pk(bq.x, bq.y); acc[t][1] = pk(bq.z, bq.w);
            acc[t][2] = pk(bR.x, bR.y); acc[t][3] = pk(bR.z, bR.w);
            acc[t][4] = pk(bm.x, bm.y); acc[t][5] = pk(bm.z, bm.w);
        }

        #pragma unroll
        for (int b = 0; b < BB; b++) {
            ulonglong2 f0 = *reinterpret_cast<const ulonglong2*>(&sWf[b * 3 * CC + c0]);
            ulonglong2 f1 = *reinterpret_cast<const ulonglong2*>(&sWf[b * 3 * CC + CC + c0]);
            ulonglong2 f2 = *reinterpret_cast<const ulonglong2*>(&sWf[b * 3 * CC + 2 * CC + c0]);
            #pragma unroll
            for (int t = 0; t < EPW; t++) {
                uint64_t aw = bcast2(__shfl_sync(0xFFFFFFFFu, av[t], b));
                fma2(acc[t][0], f0.x, aw); fma2(acc[t][1], f0.y, aw);
                fma2(acc[t][2], f1.x, aw); fma2(acc[t][3], f1.y, aw);
                fma2(acc[t][4], f2.x, aw); fma2(acc[t][5], f2.y, aw);
            }
        }

        #pragma unroll
        for (int t = 0; t < EPW; t++) {
            const int e = e0 + t;
            const float f = fc[t];
            const float ev0 = evs[e * 3 + 0];
            const float ev1 = evs[e * 3 + 1];
            const float ev2 = evs[e * 3 + 2];

            float2 wq0 = unpk(acc[t][0]), wq1 = unpk(acc[t][1]);
            float2 wR0 = unpk(acc[t][2]), wR1 = unpk(acc[t][3]);
            float2 wm0 = unpk(acc[t][4]), wm1 = unpk(acc[t][5]);

            const float4* xb = reinterpret_cast<const float4*>(&g_x[jj[t] * 3 * CC]);
            float4 x0 = xb[lane];
            float4 x1 = xb[32 + lane];
            float4 x2 = xb[64 + lane];

            float4 dq = make_float4(x0.x * wq0.x * f, x0.y * wq0.y * f,
                                    x0.z * wq1.x * f, x0.w * wq1.y * f);
            red4(&g_q1[ii[t] * CC + c0], dq);

            float4 cR = make_float4(x1.x * wR0.x * f, x1.y * wR0.y * f,
                                    x1.z * wR1.x * f, x1.w * wR1.y * f);
            float4 cm = make_float4(x2.x * wm0.x * f, x2.y * wm0.y * f,
                                    x2.z * wm1.x * f, x2.w * wm1.y * f);

            const float4* mub = reinterpret_cast<const float4*>(&mu[jj[t] * 3 * CC]);
            #pragma unroll
            for (int v = 0; v < 3; v++) {
                float evv = (v == 0) ? ev0 : (v == 1) ? ev1 : ev2;
                float4 mj = mub[v * 32 + lane];
                float4 dm = make_float4(fmaf(cm.x, mj.x, cR.x * evv),
                                        fmaf(cm.y, mj.y, cR.y * evv),
                                        fmaf(cm.z, mj.z, cR.z * evv),
                                        fmaf(cm.w, mj.w, cR.w * evv));
                red4(&g_mu1[(ii[t] * 3 + v) * CC + c0], dm);
            }
        }
    }
}

// ============================================================================
// K3a: mu_mix = mu1 @ W_mix -> muV, muW. mu1 treated as [3N,128].
// Both output groups fused; Wmix staged via cp.async (8 k-rows x 256 / tile).
// ============================================================================
#define K3R 8
#define K3T (CC / K3R)   // 16 tiles

__global__ __launch_bounds__(256) void k_mumix(const float* __restrict__ Wmix)
{
    __shared__ __align__(16) float sT[CC * STR];
    __shared__ __align__(16) float sW[2][K3R * 2 * CC];   // 2 x 2048 floats
    const int tid  = threadIdx.x;
    const int d    = tid & 127;
    const int h    = tid >> 7;
    const int base = blockIdx.x * NPB;
    const uint32_t swb0 = (uint32_t)__cvta_generic_to_shared(sW[0]);
    const uint32_t swb1 = (uint32_t)__cvta_generic_to_shared(sW[1]);

    #pragma unroll
    for (int n2 = 0; n2 < NH; n2++) {
        const int r = n2 * 2 + h;
        sT[d * STR + r] = g_mu1[(base + r) * CC + d];
    }
    __syncthreads();

    uint64_t acc[2][4];
    #pragma unroll
    for (int g = 0; g < 2; g++)
        #pragma unroll
        for (int m = 0; m < 4; m++) acc[g][m] = 0ull;

    #pragma unroll
    for (int t = tid; t < K3R * 2 * CC / 4; t += 256)
        cpa16(swb0 + t * 16, Wmix + t * 4);
    CP_COMMIT();

    for (int kt = 0; kt < K3T; kt++) {
        CP_WAIT0();
        __syncthreads();
        if (kt + 1 < K3T) {
            const float* src = Wmix + (kt + 1) * K3R * 2 * CC;
            uint32_t dstb = ((kt + 1) & 1) ? swb1 : swb0;
            #pragma unroll
            for (int t = tid; t < K3R * 2 * CC / 4; t += 256)
                cpa16(dstb + t * 16, src + t * 4);
            CP_COMMIT();
        }
        const float* sWt = sW[kt & 1];
        #pragma unroll
        for (int r = 0; r < K3R; r++) {
            const int k = kt * K3R + r;
            uint64_t w0 = bcast2(sWt[r * 2 * CC + 0 * CC + d]);
            uint64_t w1 = bcast2(sWt[r * 2 * CC + 1 * CC + d]);
            const ulonglong2* row = reinterpret_cast<const ulonglong2*>(&sT[k * STR + h * NH]);
            ulonglong2 v0 = row[0], v1 = row[1];
            fma2(acc[0][0], v0.x, w0); fma2(acc[0][1], v0.y, w0);
            fma2(acc[0][2], v1.x, w0); fma2(acc[0][3], v1.y, w0);
            fma2(acc[1][0], v0.x, w1); fma2(acc[1][1], v0.y, w1);
            fma2(acc[1][2], v1.x, w1); fma2(acc[1][3], v1.y, w1);
        }
    }
    #pragma unroll
    for (int g = 0; g < 2; g++) {
        float* dst = (g == 0) ? g_muV : g_muW;
        #pragma unroll
        for (int m = 0; m < 4; m++) {
            float2 p = unpk(acc[g][m]);
            dst[(base + h * NH + 2*m)     * CC + d] = p.x;
            dst[(base + h * NH + 2*m + 1) * CC + d] = p.y;
        }
    }
}

// ============================================================================
// K3b: mixing MLP + final outputs. cp.async weight staging on both layers.
// ctx rows 0..127 = q1 (preserved), rows 128..255 = |mu_V| then hidden.
// ============================================================================
#define K4R1 16                // layer1 tile rows (Wm1: [256][128])
#define K4T1 (2 * CC / K4R1)   // 16 tiles
#define K4R2 8                 // layer2 tile rows (Wm2: [128][384])
#define K4T2 (CC / K4R2)       // 16 tiles

__global__ __launch_bounds__(256) void k_mixout(
    const float* __restrict__ Wm1, const float* __restrict__ bm1,
    const float* __restrict__ Wm2, const float* __restrict__ bm2,
    float* __restrict__ out_q, float* __restrict__ out_mu)
{
    __shared__ __align__(16) float buf[2 * CC * STR];     // 20 KB
    __shared__ __align__(16) float sscal[NPB * CC];       //  8 KB
    __shared__ __align__(16) float sW[2][3 * CC * K4R2];  // 24 KB
    const int tid  = threadIdx.x;
    const int d    = tid & 127;
    const int h    = tid >> 7;
    const int base = blockIdx.x * NPB;
    const uint32_t swb0 = (uint32_t)__cvta_generic_to_shared(sW[0]);
    const uint32_t swb1 = (uint32_t)__cvta_generic_to_shared(sW[1]);

    // prologue: ctx tile (q1, |mu_V|) + scal = <mu_V, mu_W> per (node,d)
    #pragma unroll
    for (int n2 = 0; n2 < NH; n2++) {
        const int n = n2 * 2 + h;
        const int node = base + n;
        float q1v = g_q1[node * CC + d];
        float v0 = g_muV[(node * 3 + 0) * CC + d];
        float v1 = g_muV[(node * 3 + 1) * CC + d];
        float v2 = g_muV[(node * 3 + 2) * CC + d];
        float w0 = g_muW[(node * 3 + 0) * CC + d];
        float w1 = g_muW[(node * 3 + 1) * CC + d];
        float w2 = g_muW[(node * 3 + 2) * CC + d];
        float vn = sqrtf(fmaf(v0, v0, fmaf(v1, v1, fmaf(v2, v2, EPS_F))));
        sscal[n * CC + d] = fmaf(v0, w0, fmaf(v1, w1, v2 * w2));
        buf[d * STR + n] = q1v;
        buf[(CC + d) * STR + n] = vn;
    }
    __syncthreads();

    // ---- layer 1: hidden = silu(ctx @ Wm1 + bm1) ----
    uint64_t acc[4];
    {
        float bb = bm1[d];
        uint64_t bi = pk(bb, bb);
        #pragma unroll
        for (int m = 0; m < 4; m++) acc[m] = bi;

        #pragma unroll
        for (int t = tid; t < K4R1 * CC / 4; t += 256)
            cpa16(swb0 + t * 16, Wm1 + t * 4);
        CP_COMMIT();

        for (int kt = 0; kt < K4T1; kt++) {
            CP_WAIT0();
            __syncthreads();
            if (kt + 1 < K4T1) {
                const float* src = Wm1 + (kt + 1) * K4R1 * CC;
                uint32_t dstb = ((kt + 1) & 1) ? swb1 : swb0;
                #pragma unroll
                for (int t = tid; t < K4R1 * CC / 4; t += 256)
                    cpa16(dstb + t * 16, src + t * 4);
                CP_COMMIT();
            }
            const float* sWt = sW[kt & 1];
            #pragma unroll
            for (int r = 0; r < K4R1; r++) {
                const int k = kt * K4R1 + r;
                uint64_t ww = bcast2(sWt[r * CC + d]);
                const ulonglong2* row = reinterpret_cast<const ulonglong2*>(&buf[k * STR + h * NH]);
                ulonglong2 v0 = row[0], v1 = row[1];
                fma2(acc[0], v0.x, ww); fma2(acc[1], v0.y, ww);
                fma2(acc[2], v1.x, ww); fma2(acc[3], v1.y, ww);
            }
        }
    }
    __syncthreads();   // all ctx reads done; overwrite vn rows (128..255) w/ hidden
    #pragma unroll
    for (int m = 0; m < 4; m++) {
        float2 p = unpk(acc[m]);
        buf[(CC + d) * STR + h * NH + 2*m]     = siluf(p.x);
        buf[(CC + d) * STR + h * NH + 2*m + 1] = siluf(p.y);
    }
    __syncthreads();

    // ---- layer 2: 3 output groups fused, over hidden rows ----
    uint64_t a[3][4];
    #pragma unroll
    for (int g = 0; g < 3; g++) {
        float bb = bm2[g * CC + d];
        uint64_t bi = pk(bb, bb);
        #pragma unroll
        for (int m = 0; m < 4; m++) a[g][m] = bi;
    }
    #pragma unroll
    for (int t = tid; t < K4R2 * 3 * CC / 4; t += 256)
        cpa16(swb0 + t * 16, Wm2 + t * 4);
    CP_COMMIT();

    for (int kt = 0; kt < K4T2; kt++) {
        CP_WAIT0();
        __syncthreads();
        if (kt + 1 < K4T2) {
            const float* src = Wm2 + (kt + 1) * K4R2 * 3 * CC;
            uint32_t dstb = ((kt + 1) & 1) ? swb1 : swb0;
            #pragma unroll
            for (int t = tid; t < K4R2 * 3 * CC / 4; t += 256)
                cpa16(dstb + t * 16, src + t * 4);
            CP_COMMIT();
        }
        const float* sWt = sW[kt & 1];
        #pragma unroll
        for (int r = 0; r < K4R2; r++) {
            const int k = kt * K4R2 + r;
            uint64_t w0 = bcast2(sWt[r * 3 * CC + 0 * CC + d]);
            uint64_t w1 = bcast2(sWt[r * 3 * CC + 1 * CC + d]);
            uint64_t w2 = bcast2(sWt[r * 3 * CC + 2 * CC + d]);
            const ulonglong2* row = reinterpret_cast<const ulonglong2*>(&buf[(CC + k) * STR + h * NH]);
            ulonglong2 v0 = row[0], v1 = row[1];
            fma2(a[0][0], v0.x, w0); fma2(a[0][1], v0.y, w0);
            fma2(a[0][2], v1.x, w0); fma2(a[0][3], v1.y, w0);
            fma2(a[1][0], v0.x, w1); fma2(a[1][1], v0.y, w1);
            fma2(a[1][2], v1.x, w1); fma2(a[1][3], v1.y, w1);
            fma2(a[2][0], v0.x, w2); fma2(a[2][1], v0.y, w2);
            fma2(a[2][2], v1.x, w2); fma2(a[2][3], v1.y, w2);
        }
    }

    // epilogue
    #pragma unroll
    for (int m = 0; m < 4; m++) {
        float2 p0 = unpk(a[0][m]);   // dq_intra
        float2 p1 = unpk(a[1][m]);   // dmu_intra
        float2 p2 = unpk(a[2][m]);   // dqmu_intra
        #pragma unroll
        for (int t = 0; t < 2; t++) {
            const int n = h * NH + 2*m + t;
            const int node = base + n;
            float y0 = t ? p0.y : p0.x;
            float y1 = t ? p1.y : p1.x;
            float y2 = t ? p2.y : p2.x;
            float q1v  = buf[d * STR + n];          // preserved ctx row
            float scal = sscal[n * CC + d];
            out_q[node * CC + d] = q1v + y0 + y2 * scal;
            #pragma unroll
            for (int v = 0; v < 3; v++) {
                float mw = g_muW[(node * 3 + v) * CC + d];
                float m1 = g_mu1[(node * 3 + v) * CC + d];
                out_mu[(node * 3 + v) * CC + d] = fmaf(y1, mw, m1);
            }
        }
    }
}

// ============================================================================
extern "C" void kernel_launch(void* const* d_in, const int* in_sizes, int n_in,
                              void* d_out, int out_size)
{
    const float* q     = (const float*)d_in[0];
    const float* mu    = (const float*)d_in[1];
    const int*   eidx  = (const int*)  d_in[2];
    const float* ew    = (const float*)d_in[3];
    const float* evs   = (const float*)d_in[4];
    const float* attrs = (const float*)d_in[5];
    const float* Wf    = (const float*)d_in[6];
    const float* bf    = (const float*)d_in[7];
    const float* W1    = (const float*)d_in[8];
    const float* b1    = (const float*)d_in[9];
    const float* W2    = (const float*)d_in[10];
    const float* b2    = (const float*)d_in[11];
    const float* Wmix  = (const float*)d_in[12];
    const float* Wm1   = (const float*)d_in[13];
    const float* bm1   = (const float*)d_in[14];
    const float* Wm2   = (const float*)d_in[15];
    const float* bm2   = (const float*)d_in[16];

    float* out_q  = (float*)d_out;
    float* out_mu = out_q + (size_t)NN * CC;

    k_context<<<NN / NPB, 256>>>(q, mu, W1, b1, W2, b2);
    k_edge<<<1184, 256>>>(eidx, ew, evs, attrs, Wf, bf, mu);
    k_mumix<<<(3 * NN) / NPB, 256>>>(Wmix);
    k_mixout<<<NN / NPB, 256>>>(Wm1, bm1, Wm2, bm2, out_q, out_mu);
}